// round 8
// baseline (speedup 1.0000x reference)
#include <cuda_runtime.h>
#include <cstdint>

#define N_NODES 50000
#define N_EDGES 640000
#define D 128
#define N_RELS 16
#define N_NT 8
#define TILE 128

#define EG (N_EDGES / TILE + N_RELS)
#define NG ((N_NODES + TILE - 1) / TILE + N_NT)
#define E_PAD (EG * TILE)
#define N_PAD (NG * TILE)

#define SROW 136                          /* padded row stride: bank-clean for LDS.64 */
#define EDGE_SMEM ((128 + 64) * SROW * 4) /* sA(128 rows) + sB(64 rows) = 104448 B */
#define NSROW 132
#define NODE_SMEM (2 * 128 * NSROW * 4)
#define SETUP_GRID 148

/* ------------------------------ scratch ------------------------------ */
__device__ int   g_counts[N_NODES * N_RELS];
__device__ int   g_rel_cnt[N_RELS];
__device__ int   g_rel_cur[N_RELS];
__device__ int   g_nt_cnt[N_NT];
__device__ int   g_nt_cur[N_NT];
__device__ int   g_eperm[E_PAD];
__device__ int   g_esrc[E_PAD];
__device__ int   g_edst[E_PAD];
__device__ float g_einv[E_PAD];
__device__ int   g_erel[E_PAD];
__device__ int   g_nperm[N_PAD];
__device__ float g_agg[N_NODES * D];
__device__ int   g_ntiles[2];
__device__ float g_WT[N_RELS * D * D];   /* W_edge^T, tf32-rounded, pair-interleaved phi(k) */
__device__ float g_WnT[N_NT * D * D];    /* W_node^T, plain layout */
__device__ float g_featsR[N_NODES * D];
__device__ int   g_barrier_cnt;

/* ------------------------------ helpers ------------------------------ */
__device__ __forceinline__ uint32_t tf32r(float x) {
    uint32_t r;
    asm("cvt.rna.tf32.f32 %0, %1;" : "=r"(r) : "f"(x));
    return r;
}
__device__ __forceinline__ void mma8(float* c, const uint32_t* a, const uint32_t* b) {
    asm volatile(
        "mma.sync.aligned.m16n8k8.row.col.f32.tf32.tf32.f32 "
        "{%0,%1,%2,%3}, {%4,%5,%6,%7}, {%8,%9}, {%0,%1,%2,%3};"
        : "+f"(c[0]), "+f"(c[1]), "+f"(c[2]), "+f"(c[3])
        : "r"(a[0]), "r"(a[1]), "r"(a[2]), "r"(a[3]), "r"(b[0]), "r"(b[1]));
}
__device__ __forceinline__ void red2(float* p, float x, float y) {
    asm volatile("red.global.add.v2.f32 [%0], {%1,%2};" :: "l"(p), "f"(x), "f"(y) : "memory");
}
__device__ __forceinline__ void gsync(int phase) {
    __syncthreads();
    if (threadIdx.x == 0) {
        __threadfence();
        atomicAdd(&g_barrier_cnt, 1);
        while (atomicAdd(&g_barrier_cnt, 0) < SETUP_GRID * phase) {}
    }
    __syncthreads();
}
/* pair-interleave: phi(k) = (k>>3)*8 + (k&3)*2 + ((k>>2)&1) */
__device__ __forceinline__ int phik(int k) {
    return ((k >> 3) << 3) + ((k & 3) << 1) + ((k >> 2) & 1);
}

/* ------------------------------ setup: zero + round + transpose ------------------------------ */
__global__ void k_zerowt(const float* __restrict__ feats, const float* __restrict__ We,
                         const float* __restrict__ Wn) {
    int i = blockIdx.x * blockDim.x + threadIdx.x;
    int stride = gridDim.x * blockDim.x;
    for (int j = i; j < N_NODES * D; j += stride) {
        g_agg[j] = 0.0f;
        g_featsR[j] = __uint_as_float(tf32r(feats[j]));
    }
    for (int j = i; j < N_NODES * N_RELS; j += stride) g_counts[j] = 0;
    for (int j = i; j < E_PAD; j += stride) {
        g_edst[j] = -1;
        g_esrc[j] = 0;
        g_einv[j] = 0.0f;
    }
    for (int j = i; j < N_PAD; j += stride) g_nperm[j] = -1;
    if (i < N_RELS) g_rel_cnt[i] = 0;
    if (i < N_NT) g_nt_cnt[i] = 0;
    if (i == 0) g_barrier_cnt = 0;
    for (int j = i; j < N_RELS * D * D; j += stride) {
        int m = j >> 14, lin = j & 16383;
        int f = lin >> 7, d = lin & 127;
        g_WT[(size_t)m * D * D + f * D + phik(d)] =
            __uint_as_float(tf32r(We[(size_t)m * D * D + d * D + f]));
    }
    for (int j = i; j < N_NT * D * D; j += stride) {
        int m = j >> 14, lin = j & 16383;
        int f = lin >> 7, d = lin & 127;
        g_WnT[(size_t)m * D * D + f * D + d] =
            __uint_as_float(tf32r(Wn[(size_t)m * D * D + d * D + f]));
    }
}

/* ------------------------------ setup: hist + scan + scatter (+ per-edge meta) ------------------------------ */
__global__ __launch_bounds__(256, 1) void k_sortall(
    const int* __restrict__ src, const int* __restrict__ dst,
    const int* __restrict__ etypes, const int* __restrict__ ntypes) {
    __shared__ int sh[N_RELS + N_NT];
    __shared__ int s_cnt[N_RELS], s_base[N_RELS];
    const int tid = threadIdx.x;

    if (tid < N_RELS + N_NT) sh[tid] = 0;
    __syncthreads();
    int i = blockIdx.x * blockDim.x + tid;
    int stride = gridDim.x * blockDim.x;
    for (int e = i; e < N_EDGES; e += stride) {
        int t = etypes[e];
        atomicAdd(&sh[t], 1);
        atomicAdd(&g_counts[dst[e] * N_RELS + t], 1);
    }
    for (int n = i; n < N_NODES; n += stride) atomicAdd(&sh[N_RELS + ntypes[n]], 1);
    __syncthreads();
    if (tid < N_RELS) atomicAdd(&g_rel_cnt[tid], sh[tid]);
    else if (tid < N_RELS + N_NT) atomicAdd(&g_nt_cnt[tid - N_RELS], sh[tid]);

    gsync(1);

    if (blockIdx.x == 0 && tid == 0) {
        int off = 0;
        for (int t = 0; t < N_RELS; t++) {
            g_rel_cur[t] = off;
            off += ((g_rel_cnt[t] + TILE - 1) / TILE) * TILE;
        }
        g_ntiles[0] = off / TILE;
        off = 0;
        for (int t = 0; t < N_NT; t++) {
            g_nt_cur[t] = off;
            off += ((g_nt_cnt[t] + TILE - 1) / TILE) * TILE;
        }
        g_ntiles[1] = off / TILE;
        __threadfence();
    }

    gsync(2);

    const int CH = 2048;
    int nch = (N_EDGES + CH - 1) / CH;
    for (int ch = blockIdx.x; ch < nch; ch += gridDim.x) {
        int lo = ch * CH, hi = min(lo + CH, N_EDGES);
        if (tid < N_RELS) s_cnt[tid] = 0;
        __syncthreads();
        for (int e = lo + tid; e < hi; e += blockDim.x) atomicAdd(&s_cnt[etypes[e]], 1);
        __syncthreads();
        if (tid < N_RELS) {
            s_base[tid] = atomicAdd(&g_rel_cur[tid], s_cnt[tid]);
            s_cnt[tid] = 0;
        }
        __syncthreads();
        for (int e = lo + tid; e < hi; e += blockDim.x) {
            int t = etypes[e];
            int pos = s_base[t] + atomicAdd(&s_cnt[t], 1);
            int dn = dst[e];
            g_eperm[pos] = e;
            g_esrc[pos] = src[e];
            g_edst[pos] = dn;
            g_erel[pos] = t;
            g_einv[pos] = 1.0f / (float)g_counts[dn * N_RELS + t];
        }
        __syncthreads();
    }
    nch = (N_NODES + CH - 1) / CH;
    for (int ch = blockIdx.x; ch < nch; ch += gridDim.x) {
        int lo = ch * CH, hi = min(lo + CH, N_NODES);
        if (tid < N_NT) s_cnt[tid] = 0;
        __syncthreads();
        for (int n = lo + tid; n < hi; n += blockDim.x) atomicAdd(&s_cnt[ntypes[n]], 1);
        __syncthreads();
        if (tid < N_NT) {
            s_base[tid] = atomicAdd(&g_nt_cur[tid], s_cnt[tid]);
            s_cnt[tid] = 0;
        }
        __syncthreads();
        for (int n = lo + tid; n < hi; n += blockDim.x) {
            int t = ntypes[n];
            g_nperm[s_base[t] + atomicAdd(&s_cnt[t], 1)] = n;
        }
        __syncthreads();
    }
}

__global__ void k_nop() {}

/* ------------------------------ edge GEMM: 128x64 half-tile per CTA, 256 thr ------------------------------ */
/* Two CTAs per tile (N halves); 2 co-resident CTAs/SM. Warp grid 4m x 2n, 32x32
 * warp tiles, paired-k float2 fragment loads, reg-direct red.v2 epilogue. */
__global__ __launch_bounds__(256, 2) void k_edge_v8(const float* __restrict__ b_edge) {
    const int tile = blockIdx.x >> 1;
    if (tile >= g_ntiles[0]) return;
    const int c0 = (blockIdx.x & 1) * 64;   /* this CTA's column half */

    extern __shared__ float smf[];
    float* sA = smf;                   /* [128][SROW], phi-interleaved k */
    float* sB = smf + 128 * SROW;      /* [64][SROW],  phi-interleaved k */

    __shared__ int sDst[TILE];
    __shared__ float sInv[TILE];
    __shared__ float sBias[64];
    __shared__ int sRel;

    const int tid = threadIdx.x;
    const int base = tile * TILE;
    const int r = tid >> 1, h = tid & 1;

    /* coalesced meta */
    if (h == 0) {
        sDst[r] = g_edst[base + r];
        sInv[r] = g_einv[base + r];
    }
    if (tid == 0) sRel = g_erel[base];

    /* gather A rows, interleaving pairs (k, k+4) in registers; 2 threads/row */
    {
        int s = g_esrc[base + r];
        const float4* fp = (const float4*)(g_featsR + (size_t)s * D);
        float* ap = sA + r * SROW;
#pragma unroll
        for (int i = 0; i < 8; i++) {
            int g = h * 8 + i;
            float4 v1 = fp[g * 2];
            float4 v2 = fp[g * 2 + 1];
            float4 w1 = make_float4(v1.x, v2.x, v1.y, v2.y);
            float4 w2 = make_float4(v1.z, v2.z, v1.w, v2.w);
            *(float4*)(ap + g * 8) = w1;
            *(float4*)(ap + g * 8 + 4) = w2;
        }
    }
    __syncthreads();

    const int rel = sRel;
    /* B copy: this CTA's 64 rows of W^T (already phi-interleaved) */
    {
        const float* Wr = g_WT + (size_t)rel * D * D + (size_t)c0 * D;
#pragma unroll
        for (int i = 0; i < 8; i++) {
            int lin = tid + 256 * i;        /* float4 id, 64*32 = 2048 total */
            int f = lin >> 5, wq = lin & 31;
            *(float4*)(sB + f * SROW + wq * 4) = *(const float4*)(Wr + f * D + wq * 4);
        }
    }
    if (tid < 64) sBias[tid] = b_edge[rel * D + c0 + tid];
    __syncthreads();

    const int wid = tid >> 5, lane = tid & 31;
    const int wm = wid & 3, wn = wid >> 2;         /* 4m x 2n */
    const int r_base = wm * 32, cl = wn * 32;      /* local col base */
    const int lq = lane >> 2, lr = lane & 3;

    float acc[2][4][4];
#pragma unroll
    for (int mt = 0; mt < 2; mt++)
#pragma unroll
        for (int nt = 0; nt < 4; nt++)
#pragma unroll
            for (int j = 0; j < 4; j++) acc[mt][nt][j] = 0.0f;

#pragma unroll 4
    for (int k0 = 0; k0 < 16; k0++) {
        const int kb = k0 * 8 + lr * 2;
        uint32_t a[2][4], bb[4][2];
#pragma unroll
        for (int mt = 0; mt < 2; mt++) {
            int row = r_base + mt * 16 + lq;
            float2 p0 = *(const float2*)(sA + row * SROW + kb);
            float2 p1 = *(const float2*)(sA + (row + 8) * SROW + kb);
            a[mt][0] = __float_as_uint(p0.x);
            a[mt][1] = __float_as_uint(p1.x);
            a[mt][2] = __float_as_uint(p0.y);
            a[mt][3] = __float_as_uint(p1.y);
        }
#pragma unroll
        for (int nt = 0; nt < 4; nt++) {
            int n = cl + nt * 8 + lq;
            float2 pb = *(const float2*)(sB + n * SROW + kb);
            bb[nt][0] = __float_as_uint(pb.x);
            bb[nt][1] = __float_as_uint(pb.y);
        }
#pragma unroll
        for (int mt = 0; mt < 2; mt++)
#pragma unroll
            for (int nt = 0; nt < 4; nt++) mma8(acc[mt][nt], a[mt], bb[nt]);
    }

    /* epilogue: (acc + bias) * inv -> red.v2, no barrier */
#pragma unroll
    for (int mt = 0; mt < 2; mt++)
#pragma unroll
        for (int hh = 0; hh < 2; hh++) {
            int rr = r_base + mt * 16 + lq + hh * 8;
            int dn = sDst[rr];
            if (dn < 0) continue;
            float inv = sInv[rr];
            float* gb = g_agg + (size_t)dn * D + c0;
#pragma unroll
            for (int nt = 0; nt < 4; nt++) {
                int col = cl + nt * 8 + lr * 2;
                float x = (acc[mt][nt][hh * 2 + 0] + sBias[col]) * inv;
                float y = (acc[mt][nt][hh * 2 + 1] + sBias[col + 1]) * inv;
                red2(gb + col, x, y);
            }
        }
}

/* ------------------------------ node GEMM + residual + relu ------------------------------ */
__global__ __launch_bounds__(256, 1) void k_node_mma(
    const float* __restrict__ b_node, const int* __restrict__ ntypes,
    float* __restrict__ out) {
    if ((int)blockIdx.x >= g_ntiles[1]) return;

    extern __shared__ float smf[];
    float* sA = smf;
    float* sB = smf + 128 * NSROW;
    const uint32_t* sAu = (const uint32_t*)sA;
    const uint32_t* sBu = (const uint32_t*)sB;

    __shared__ int sNode[TILE];
    __shared__ float sBias[TILE];
    __shared__ int sNt;

    const int tid = threadIdx.x, wid = tid >> 5, lane = tid & 31;
    const int base = blockIdx.x * TILE;

    if (tid < TILE) {
        int n = g_nperm[base + tid];
        sNode[tid] = n;
        if (tid == 0) sNt = ntypes[n];
    }
    __syncthreads();
    const int nt_ = sNt;
    if (tid < TILE) sBias[tid] = b_node[nt_ * D + tid];

    {
        int r = tid >> 1, half = tid & 1;
        int n = sNode[r];
        const float4* fp = (const float4*)(g_featsR + (size_t)(n >= 0 ? n : 0) * D) + half * 16;
        float* ap = sA + r * NSROW + half * 64;
#pragma unroll
        for (int i = 0; i < 16; i++) *(float4*)(ap + i * 4) = fp[i];
    }
    {
        const float* Wr = g_WnT + (size_t)nt_ * D * D;
#pragma unroll
        for (int i = 0; i < 16; i++) {
            int lin = tid + 256 * i;
            int f = lin >> 5, kq = lin & 31;
            *(float4*)(sB + f * NSROW + kq * 4) = *(const float4*)(Wr + f * D + kq * 4);
        }
    }
    __syncthreads();

    const int wm = wid & 1, wn = wid >> 1;
    const int r_base = wm * 64, c_base = wn * 32;
    const int lq = lane >> 2, lr = lane & 3;

    float acc[4][4][4];
#pragma unroll
    for (int mt = 0; mt < 4; mt++)
#pragma unroll
        for (int ntl = 0; ntl < 4; ntl++)
#pragma unroll
            for (int j = 0; j < 4; j++) acc[mt][ntl][j] = 0.0f;

#pragma unroll 4
    for (int k0 = 0; k0 < 16; k0++) {
        const int kk = k0 * 8 + lr;
        uint32_t a[4][4], b[4][2];
#pragma unroll
        for (int mt = 0; mt < 4; mt++) {
            int row = r_base + mt * 16 + lq;
            a[mt][0] = sAu[row * NSROW + kk];
            a[mt][1] = sAu[(row + 8) * NSROW + kk];
            a[mt][2] = sAu[row * NSROW + kk + 4];
            a[mt][3] = sAu[(row + 8) * NSROW + kk + 4];
        }
#pragma unroll
        for (int ntl = 0; ntl < 4; ntl++) {
            int n = c_base + ntl * 8 + lq;
            b[ntl][0] = sBu[n * NSROW + kk];
            b[ntl][1] = sBu[n * NSROW + kk + 4];
        }
#pragma unroll
        for (int mt = 0; mt < 4; mt++)
#pragma unroll
            for (int ntl = 0; ntl < 4; ntl++) mma8(acc[mt][ntl], a[mt], b[ntl]);
    }

#pragma unroll
    for (int mt = 0; mt < 4; mt++) {
        int row0 = r_base + mt * 16 + lq;
#pragma unroll
        for (int h = 0; h < 2; h++) {
            int rr = row0 + h * 8;
            int n = sNode[rr];
            if (n < 0) continue;
            const float* ab = g_agg + (size_t)n * D;
            float* ob = out + (size_t)n * D;
#pragma unroll
            for (int ntl = 0; ntl < 4; ntl++) {
                int col = c_base + ntl * 8 + lr * 2;
                float2 ag = *(const float2*)(ab + col);
                float2 o;
                o.x = fmaxf(acc[mt][ntl][h * 2 + 0] + sBias[col] + ag.x, 0.0f);
                o.y = fmaxf(acc[mt][ntl][h * 2 + 1] + sBias[col + 1] + ag.y, 0.0f);
                *(float2*)(ob + col) = o;
            }
        }
    }
}

/* ------------------------------ launch ------------------------------ */
extern "C" void kernel_launch(void* const* d_in, const int* in_sizes, int n_in,
                              void* d_out, int out_size) {
    const float* feats  = (const float*)d_in[0];
    const float* W_edge = (const float*)d_in[1];
    const float* b_edge = (const float*)d_in[2];
    const float* W_node = (const float*)d_in[3];
    const float* b_node = (const float*)d_in[4];
    const int* src    = (const int*)d_in[5];
    const int* dst    = (const int*)d_in[6];
    const int* ntypes = (const int*)d_in[7];
    const int* etypes = (const int*)d_in[8];
    float* out = (float*)d_out;
    (void)in_sizes; (void)n_in; (void)out_size;

    cudaFuncSetAttribute(k_edge_v8, cudaFuncAttributeMaxDynamicSharedMemorySize, EDGE_SMEM);
    cudaFuncSetAttribute(k_node_mma, cudaFuncAttributeMaxDynamicSharedMemorySize, NODE_SMEM);

    k_zerowt<<<1024, 256>>>(feats, W_edge, W_node);
    k_sortall<<<SETUP_GRID, 256>>>(src, dst, etypes, ntypes);
    k_nop<<<1, 1>>>();
    k_edge_v8<<<2 * EG, 256, EDGE_SMEM>>>(b_edge);
    k_node_mma<<<NG, 256, NODE_SMEM>>>(b_node, ntypes, out);
}

// round 9
// speedup vs baseline: 1.2486x; 1.2486x over previous
#include <cuda_runtime.h>
#include <cstdint>

#define N_NODES 50000
#define N_EDGES 640000
#define D 128
#define N_RELS 16
#define N_NT 8
#define TILE 128

#define EG (N_EDGES / TILE + N_RELS)
#define NG ((N_NODES + TILE - 1) / TILE + N_NT)
#define E_PAD (EG * TILE)
#define N_PAD (NG * TILE)

#define SROW 136                          /* padded row stride: bank-clean for LDS.64 */
#define EDGE_SMEM (2 * 128 * SROW * 4)    /* sA + sB = 139264 B */
#define NSROW 132
#define NODE_SMEM (2 * 128 * NSROW * 4)
#define SETUP_GRID 148

/* ------------------------------ scratch ------------------------------ */
__device__ int   g_counts[N_NODES * N_RELS];
__device__ int   g_rel_cnt[N_RELS];
__device__ int   g_rel_cur[N_RELS];
__device__ int   g_nt_cnt[N_NT];
__device__ int   g_nt_cur[N_NT];
__device__ int   g_esrc[E_PAD];
__device__ int   g_edst[E_PAD];
__device__ float g_einv[E_PAD];
__device__ int   g_erel[E_PAD];
__device__ int   g_nperm[N_PAD];
__device__ float g_agg[N_NODES * D];
__device__ int   g_ntiles[2];
__device__ float g_WT[N_RELS * D * D];   /* W_edge^T, tf32, phi(k)-interleaved, pi(f)-row-permuted */
__device__ float g_WnT[N_NT * D * D];    /* W_node^T, plain layout */
__device__ float g_featsR[N_NODES * D];
__device__ int   g_barrier_cnt;

/* ------------------------------ helpers ------------------------------ */
__device__ __forceinline__ uint32_t tf32r(float x) {
    uint32_t r;
    asm("cvt.rna.tf32.f32 %0, %1;" : "=r"(r) : "f"(x));
    return r;
}
__device__ __forceinline__ void mma8(float* c, const uint32_t* a, const uint32_t* b) {
    asm volatile(
        "mma.sync.aligned.m16n8k8.row.col.f32.tf32.tf32.f32 "
        "{%0,%1,%2,%3}, {%4,%5,%6,%7}, {%8,%9}, {%0,%1,%2,%3};"
        : "+f"(c[0]), "+f"(c[1]), "+f"(c[2]), "+f"(c[3])
        : "r"(a[0]), "r"(a[1]), "r"(a[2]), "r"(a[3]), "r"(b[0]), "r"(b[1]));
}
__device__ __forceinline__ void red4(float* p, float x, float y, float z, float w) {
    asm volatile("red.global.add.v4.f32 [%0], {%1,%2,%3,%4};"
                 :: "l"(p), "f"(x), "f"(y), "f"(z), "f"(w) : "memory");
}
__device__ __forceinline__ void gsync(int phase) {
    __syncthreads();
    if (threadIdx.x == 0) {
        __threadfence();
        atomicAdd(&g_barrier_cnt, 1);
        while (atomicAdd(&g_barrier_cnt, 0) < SETUP_GRID * phase) {}
    }
    __syncthreads();
}
/* pair-interleave: phi(k) = (k>>3)*8 + (k&3)*2 + ((k>>2)&1) */
__device__ __forceinline__ int phik(int k) {
    return ((k >> 3) << 3) + ((k & 3) << 1) + ((k >> 2) & 1);
}
/* row permutation for v4 epilogue: within 16-row group, f=4a+2b+c -> p=8b+2a+c */
__device__ __forceinline__ int pif(int f) {
    int a = (f >> 2) & 3, b = (f >> 1) & 1, c = f & 1;
    return (f & ~15) | (b << 3) | (a << 1) | c;
}

/* ------------------------------ setup: zero + round + transpose ------------------------------ */
__global__ void k_zerowt(const float* __restrict__ feats, const float* __restrict__ We,
                         const float* __restrict__ Wn) {
    int i = blockIdx.x * blockDim.x + threadIdx.x;
    int stride = gridDim.x * blockDim.x;
    for (int j = i; j < N_NODES * D; j += stride) {
        g_agg[j] = 0.0f;
        g_featsR[j] = __uint_as_float(tf32r(feats[j]));
    }
    for (int j = i; j < N_NODES * N_RELS; j += stride) g_counts[j] = 0;
    for (int j = i; j < E_PAD; j += stride) {
        g_edst[j] = -1;
        g_esrc[j] = 0;
        g_einv[j] = 0.0f;
    }
    for (int j = i; j < N_PAD; j += stride) g_nperm[j] = -1;
    if (i < N_RELS) g_rel_cnt[i] = 0;
    if (i < N_NT) g_nt_cnt[i] = 0;
    if (i == 0) g_barrier_cnt = 0;
    /* W_edge: transpose + round + phi-interleave k + pi row permutation */
    for (int j = i; j < N_RELS * D * D; j += stride) {
        int m = j >> 14, lin = j & 16383;
        int f = lin >> 7, d = lin & 127;
        g_WT[(size_t)m * D * D + pif(f) * D + phik(d)] =
            __uint_as_float(tf32r(We[(size_t)m * D * D + d * D + f]));
    }
    for (int j = i; j < N_NT * D * D; j += stride) {
        int m = j >> 14, lin = j & 16383;
        int f = lin >> 7, d = lin & 127;
        g_WnT[(size_t)m * D * D + f * D + d] =
            __uint_as_float(tf32r(Wn[(size_t)m * D * D + d * D + f]));
    }
}

/* ------------------------------ setup: hist + scan + scatter (+ per-edge meta) ------------------------------ */
__global__ __launch_bounds__(256, 1) void k_sortall(
    const int* __restrict__ src, const int* __restrict__ dst,
    const int* __restrict__ etypes, const int* __restrict__ ntypes) {
    __shared__ int sh[N_RELS + N_NT];
    __shared__ int s_cnt[N_RELS], s_base[N_RELS];
    const int tid = threadIdx.x;

    if (tid < N_RELS + N_NT) sh[tid] = 0;
    __syncthreads();
    int i = blockIdx.x * blockDim.x + tid;
    int stride = gridDim.x * blockDim.x;
    for (int e = i; e < N_EDGES; e += stride) {
        int t = etypes[e];
        atomicAdd(&sh[t], 1);
        atomicAdd(&g_counts[dst[e] * N_RELS + t], 1);
    }
    for (int n = i; n < N_NODES; n += stride) atomicAdd(&sh[N_RELS + ntypes[n]], 1);
    __syncthreads();
    if (tid < N_RELS) atomicAdd(&g_rel_cnt[tid], sh[tid]);
    else if (tid < N_RELS + N_NT) atomicAdd(&g_nt_cnt[tid - N_RELS], sh[tid]);

    gsync(1);

    if (blockIdx.x == 0 && tid == 0) {
        int off = 0;
        for (int t = 0; t < N_RELS; t++) {
            g_rel_cur[t] = off;
            off += ((g_rel_cnt[t] + TILE - 1) / TILE) * TILE;
        }
        g_ntiles[0] = off / TILE;
        off = 0;
        for (int t = 0; t < N_NT; t++) {
            g_nt_cur[t] = off;
            off += ((g_nt_cnt[t] + TILE - 1) / TILE) * TILE;
        }
        g_ntiles[1] = off / TILE;
        __threadfence();
    }

    gsync(2);

    const int CH = 2048;
    int nch = (N_EDGES + CH - 1) / CH;
    for (int ch = blockIdx.x; ch < nch; ch += gridDim.x) {
        int lo = ch * CH, hi = min(lo + CH, N_EDGES);
        if (tid < N_RELS) s_cnt[tid] = 0;
        __syncthreads();
        for (int e = lo + tid; e < hi; e += blockDim.x) atomicAdd(&s_cnt[etypes[e]], 1);
        __syncthreads();
        if (tid < N_RELS) {
            s_base[tid] = atomicAdd(&g_rel_cur[tid], s_cnt[tid]);
            s_cnt[tid] = 0;
        }
        __syncthreads();
        for (int e = lo + tid; e < hi; e += blockDim.x) {
            int t = etypes[e];
            int pos = s_base[t] + atomicAdd(&s_cnt[t], 1);
            int dn = dst[e];
            g_esrc[pos] = src[e];
            g_edst[pos] = dn;
            g_erel[pos] = t;
            g_einv[pos] = 1.0f / (float)g_counts[dn * N_RELS + t];
        }
        __syncthreads();
    }
    nch = (N_NODES + CH - 1) / CH;
    for (int ch = blockIdx.x; ch < nch; ch += gridDim.x) {
        int lo = ch * CH, hi = min(lo + CH, N_NODES);
        if (tid < N_NT) s_cnt[tid] = 0;
        __syncthreads();
        for (int n = lo + tid; n < hi; n += blockDim.x) atomicAdd(&s_cnt[ntypes[n]], 1);
        __syncthreads();
        if (tid < N_NT) {
            s_base[tid] = atomicAdd(&g_nt_cur[tid], s_cnt[tid]);
            s_cnt[tid] = 0;
        }
        __syncthreads();
        for (int n = lo + tid; n < hi; n += blockDim.x) {
            int t = ntypes[n];
            g_nperm[s_base[t] + atomicAdd(&s_cnt[t], 1)] = n;
        }
        __syncthreads();
    }
}

__global__ void k_nop() {}

/* ------------------------------ edge GEMM: one tile per CTA, 512 thr ------------------------------ */
/* Warp grid 4m x 4n, 32x32 warp tiles, paired-k float2 fragment loads.
 * B rows pi-permuted at setup => each thread owns 4 consecutive logical columns
 * per n-tile pair => epilogue is 8x red.global.add.v4 per thread (half the LSU lanes). */
__global__ __launch_bounds__(512, 1) void k_edge_v9(const float* __restrict__ b_edge) {
    if ((int)blockIdx.x >= g_ntiles[0]) return;

    extern __shared__ float smf[];
    float* sA = smf;                   /* [128][SROW], phi-interleaved k */
    float* sB = smf + 128 * SROW;      /* [128][SROW], phi-interleaved k, pi-permuted rows */

    __shared__ int sDst[TILE];
    __shared__ float sInv[TILE];
    __shared__ float sBias[TILE];      /* logical column indexing */
    __shared__ int sRel;

    const int tid = threadIdx.x;
    const int base = blockIdx.x * TILE;
    const int r = tid >> 2, q = tid & 3;

    if (q == 0) {
        sDst[r] = g_edst[base + r];
        sInv[r] = g_einv[base + r];
    }
    if (tid == 0) sRel = g_erel[base];

    /* gather A rows, interleaving pairs (k, k+4) in registers */
    {
        int s = g_esrc[base + r];
        const float4* fp = (const float4*)(g_featsR + (size_t)s * D);
        float* ap = sA + r * SROW;
#pragma unroll
        for (int i = 0; i < 4; i++) {
            int g = q * 4 + i;
            float4 v1 = fp[g * 2];
            float4 v2 = fp[g * 2 + 1];
            float4 w1 = make_float4(v1.x, v2.x, v1.y, v2.y);
            float4 w2 = make_float4(v1.z, v2.z, v1.w, v2.w);
            *(float4*)(ap + g * 8) = w1;
            *(float4*)(ap + g * 8 + 4) = w2;
        }
    }
    __syncthreads();

    const int rel = sRel;
    {
        const float* Wr = g_WT + (size_t)rel * D * D;
#pragma unroll
        for (int i = 0; i < 8; i++) {
            int lin = tid + 512 * i;
            int f = lin >> 5, wq = lin & 31;
            *(float4*)(sB + f * SROW + wq * 4) = *(const float4*)(Wr + f * D + wq * 4);
        }
    }
    if (tid < TILE) sBias[tid] = b_edge[rel * D + tid];
    __syncthreads();

    const int wid = tid >> 5, lane = tid & 31;
    const int wm = wid & 3, wn = wid >> 2;
    const int r_base = wm * 32, c_base = wn * 32;
    const int lq = lane >> 2, lr = lane & 3;

    float acc[2][4][4];
#pragma unroll
    for (int mt = 0; mt < 2; mt++)
#pragma unroll
        for (int nt = 0; nt < 4; nt++)
#pragma unroll
            for (int j = 0; j < 4; j++) acc[mt][nt][j] = 0.0f;

#pragma unroll 4
    for (int k0 = 0; k0 < 16; k0++) {
        const int kb = k0 * 8 + lr * 2;
        uint32_t a[2][4], bb[4][2];
#pragma unroll
        for (int mt = 0; mt < 2; mt++) {
            int row = r_base + mt * 16 + lq;
            float2 p0 = *(const float2*)(sA + row * SROW + kb);
            float2 p1 = *(const float2*)(sA + (row + 8) * SROW + kb);
            a[mt][0] = __float_as_uint(p0.x);
            a[mt][1] = __float_as_uint(p1.x);
            a[mt][2] = __float_as_uint(p0.y);
            a[mt][3] = __float_as_uint(p1.y);
        }
#pragma unroll
        for (int nt = 0; nt < 4; nt++) {
            int n = c_base + nt * 8 + lq;
            float2 pb = *(const float2*)(sB + n * SROW + kb);
            bb[nt][0] = __float_as_uint(pb.x);
            bb[nt][1] = __float_as_uint(pb.y);
        }
#pragma unroll
        for (int mt = 0; mt < 2; mt++)
#pragma unroll
            for (int nt = 0; nt < 4; nt++) mma8(acc[mt][nt], a[mt], bb[nt]);
    }

    /* epilogue: thread owns logical cols c_base + 16j + 4*lr .. +3 for j=0,1
     * x,y from n-tile 2j (e=0,1); z,w from n-tile 2j+1 (e=0,1). */
#pragma unroll
    for (int mt = 0; mt < 2; mt++)
#pragma unroll
        for (int h = 0; h < 2; h++) {
            int rr = r_base + mt * 16 + lq + h * 8;
            int dn = sDst[rr];
            if (dn < 0) continue;
            float inv = sInv[rr];
            float* gb = g_agg + (size_t)dn * D;
#pragma unroll
            for (int j = 0; j < 2; j++) {
                int Lc = c_base + j * 16 + 4 * lr;
                float4 bv = *(const float4*)(sBias + Lc);
                float x = (acc[mt][2 * j][h * 2 + 0] + bv.x) * inv;
                float y = (acc[mt][2 * j][h * 2 + 1] + bv.y) * inv;
                float z = (acc[mt][2 * j + 1][h * 2 + 0] + bv.z) * inv;
                float w = (acc[mt][2 * j + 1][h * 2 + 1] + bv.w) * inv;
                red4(gb + Lc, x, y, z, w);
            }
        }
}

/* ------------------------------ node GEMM + residual + relu ------------------------------ */
__global__ __launch_bounds__(256, 1) void k_node_mma(
    const float* __restrict__ b_node, const int* __restrict__ ntypes,
    float* __restrict__ out) {
    if ((int)blockIdx.x >= g_ntiles[1]) return;

    extern __shared__ float smf[];
    float* sA = smf;
    float* sB = smf + 128 * NSROW;
    const uint32_t* sAu = (const uint32_t*)sA;
    const uint32_t* sBu = (const uint32_t*)sB;

    __shared__ int sNode[TILE];
    __shared__ float sBias[TILE];
    __shared__ int sNt;

    const int tid = threadIdx.x, wid = tid >> 5, lane = tid & 31;
    const int base = blockIdx.x * TILE;

    if (tid < TILE) {
        int n = g_nperm[base + tid];
        sNode[tid] = n;
        if (tid == 0) sNt = ntypes[n];
    }
    __syncthreads();
    const int nt_ = sNt;
    if (tid < TILE) sBias[tid] = b_node[nt_ * D + tid];

    {
        int r = tid >> 1, half = tid & 1;
        int n = sNode[r];
        const float4* fp = (const float4*)(g_featsR + (size_t)(n >= 0 ? n : 0) * D) + half * 16;
        float* ap = sA + r * NSROW + half * 64;
#pragma unroll
        for (int i = 0; i < 16; i++) *(float4*)(ap + i * 4) = fp[i];
    }
    {
        const float* Wr = g_WnT + (size_t)nt_ * D * D;
#pragma unroll
        for (int i = 0; i < 16; i++) {
            int lin = tid + 256 * i;
            int f = lin >> 5, kq = lin & 31;
            *(float4*)(sB + f * NSROW + kq * 4) = *(const float4*)(Wr + f * D + kq * 4);
        }
    }
    __syncthreads();

    const int wm = wid & 1, wn = wid >> 1;
    const int r_base = wm * 64, c_base = wn * 32;
    const int lq = lane >> 2, lr = lane & 3;

    float acc[4][4][4];
#pragma unroll
    for (int mt = 0; mt < 4; mt++)
#pragma unroll
        for (int ntl = 0; ntl < 4; ntl++)
#pragma unroll
            for (int j = 0; j < 4; j++) acc[mt][ntl][j] = 0.0f;

#pragma unroll 4
    for (int k0 = 0; k0 < 16; k0++) {
        const int kk = k0 * 8 + lr;
        uint32_t a[4][4], b[4][2];
#pragma unroll
        for (int mt = 0; mt < 4; mt++) {
            int row = r_base + mt * 16 + lq;
            a[mt][0] = sAu[row * NSROW + kk];
            a[mt][1] = sAu[(row + 8) * NSROW + kk];
            a[mt][2] = sAu[row * NSROW + kk + 4];
            a[mt][3] = sAu[(row + 8) * NSROW + kk + 4];
        }
#pragma unroll
        for (int ntl = 0; ntl < 4; ntl++) {
            int n = c_base + ntl * 8 + lq;
            b[ntl][0] = sBu[n * NSROW + kk];
            b[ntl][1] = sBu[n * NSROW + kk + 4];
        }
#pragma unroll
        for (int mt = 0; mt < 4; mt++)
#pragma unroll
            for (int ntl = 0; ntl < 4; ntl++) mma8(acc[mt][ntl], a[mt], b[ntl]);
    }

#pragma unroll
    for (int mt = 0; mt < 4; mt++) {
        int row0 = r_base + mt * 16 + lq;
#pragma unroll
        for (int h = 0; h < 2; h++) {
            int rr = row0 + h * 8;
            int n = sNode[rr];
            if (n < 0) continue;
            const float* ab = g_agg + (size_t)n * D;
            float* ob = out + (size_t)n * D;
#pragma unroll
            for (int ntl = 0; ntl < 4; ntl++) {
                int col = c_base + ntl * 8 + lr * 2;
                float2 ag = *(const float2*)(ab + col);
                float2 o;
                o.x = fmaxf(acc[mt][ntl][h * 2 + 0] + sBias[col] + ag.x, 0.0f);
                o.y = fmaxf(acc[mt][ntl][h * 2 + 1] + sBias[col + 1] + ag.y, 0.0f);
                *(float2*)(ob + col) = o;
            }
        }
    }
}

/* ------------------------------ launch ------------------------------ */
extern "C" void kernel_launch(void* const* d_in, const int* in_sizes, int n_in,
                              void* d_out, int out_size) {
    const float* feats  = (const float*)d_in[0];
    const float* W_edge = (const float*)d_in[1];
    const float* b_edge = (const float*)d_in[2];
    const float* W_node = (const float*)d_in[3];
    const float* b_node = (const float*)d_in[4];
    const int* src    = (const int*)d_in[5];
    const int* dst    = (const int*)d_in[6];
    const int* ntypes = (const int*)d_in[7];
    const int* etypes = (const int*)d_in[8];
    float* out = (float*)d_out;
    (void)in_sizes; (void)n_in; (void)out_size;

    cudaFuncSetAttribute(k_edge_v9, cudaFuncAttributeMaxDynamicSharedMemorySize, EDGE_SMEM);
    cudaFuncSetAttribute(k_node_mma, cudaFuncAttributeMaxDynamicSharedMemorySize, NODE_SMEM);

    k_zerowt<<<1024, 256>>>(feats, W_edge, W_node);
    k_sortall<<<SETUP_GRID, 256>>>(src, dst, etypes, ntypes);
    k_nop<<<1, 1>>>();
    k_edge_v9<<<EG, 512, EDGE_SMEM>>>(b_edge);
    k_node_mma<<<NG, 256, NODE_SMEM>>>(b_node, ntypes, out);
}

// round 10
// speedup vs baseline: 1.3496x; 1.0809x over previous
#include <cuda_runtime.h>
#include <cstdint>

#define N_NODES 50000
#define N_EDGES 640000
#define D 128
#define N_RELS 16
#define N_NT 8
#define TILE 128

#define EG (N_EDGES / TILE + N_RELS)
#define NG ((N_NODES + TILE - 1) / TILE + N_NT)
#define E_PAD (EG * TILE)
#define N_PAD (NG * TILE)

#define SROW 136                          /* padded row stride: bank-clean for LDS.64 */
#define EDGE_SMEM (2 * 128 * SROW * 4)    /* sA + sB = 139264 B */
#define NSROW 132
#define NODE_SMEM (2 * 128 * NSROW * 4)

/* ------------------------------ scratch ------------------------------ */
__device__ int   g_counts[N_NODES * N_RELS];
__device__ int   g_rel_cnt[N_RELS];
__device__ int   g_rel_cur[N_RELS];
__device__ int   g_nt_cnt[N_NT];
__device__ int   g_nt_cur[N_NT];
__device__ int   g_esrc[E_PAD];
__device__ int   g_edst[E_PAD];
__device__ float g_einv[E_PAD];
__device__ int   g_erel[E_PAD];
__device__ int   g_nperm[N_PAD];
__device__ float g_agg[N_NODES * D];
__device__ int   g_ntiles[2];
__device__ float g_WT[N_RELS * D * D];   /* W_edge^T, tf32, phi(k)-interleaved, pi(f)-row-permuted */
__device__ float g_WnT[N_NT * D * D];    /* W_node^T, plain layout */
__device__ float g_featsR[N_NODES * D];
__device__ int   g_hist_done;

/* ------------------------------ helpers ------------------------------ */
__device__ __forceinline__ uint32_t tf32r(float x) {
    uint32_t r;
    asm("cvt.rna.tf32.f32 %0, %1;" : "=r"(r) : "f"(x));
    return r;
}
__device__ __forceinline__ uint32_t smem_u32(const void* p) {
    uint32_t a;
    asm("{ .reg .u64 t; cvta.to.shared.u64 t, %1; cvt.u32.u64 %0, t; }" : "=r"(a) : "l"(p));
    return a;
}
__device__ __forceinline__ void cpa16(uint32_t dstS, const void* src) {
    asm volatile("cp.async.cg.shared.global [%0], [%1], 16;" :: "r"(dstS), "l"(src));
}
__device__ __forceinline__ void mma8(float* c, const uint32_t* a, const uint32_t* b) {
    asm volatile(
        "mma.sync.aligned.m16n8k8.row.col.f32.tf32.tf32.f32 "
        "{%0,%1,%2,%3}, {%4,%5,%6,%7}, {%8,%9}, {%0,%1,%2,%3};"
        : "+f"(c[0]), "+f"(c[1]), "+f"(c[2]), "+f"(c[3])
        : "r"(a[0]), "r"(a[1]), "r"(a[2]), "r"(a[3]), "r"(b[0]), "r"(b[1]));
}
__device__ __forceinline__ void red4(float* p, float x, float y, float z, float w) {
    asm volatile("red.global.add.v4.f32 [%0], {%1,%2,%3,%4};"
                 :: "l"(p), "f"(x), "f"(y), "f"(z), "f"(w) : "memory");
}
/* pair-interleave: phi(k) = (k>>3)*8 + (k&3)*2 + ((k>>2)&1) */
__device__ __forceinline__ int phik(int k) {
    return ((k >> 3) << 3) + ((k & 3) << 1) + ((k >> 2) & 1);
}
/* row permutation for v4 epilogue: within 16-row group, f=4a+2b+c -> p=8b+2a+c */
__device__ __forceinline__ int pif(int f) {
    int a = (f >> 2) & 3, b = (f >> 1) & 1, c = f & 1;
    return (f & ~15) | (b << 3) | (a << 1) | c;
}

/* ------------------------------ setup: zero + round + transpose ------------------------------ */
__global__ void k_zero(const float* __restrict__ feats, const float* __restrict__ We,
                       const float* __restrict__ Wn) {
    int i = blockIdx.x * blockDim.x + threadIdx.x;
    int stride = gridDim.x * blockDim.x;
    for (int j = i; j < N_NODES * D; j += stride) {
        g_agg[j] = 0.0f;
        g_featsR[j] = __uint_as_float(tf32r(feats[j]));
    }
    for (int j = i; j < N_NODES * N_RELS; j += stride) g_counts[j] = 0;
    for (int j = i; j < E_PAD; j += stride) {
        g_edst[j] = -1;
        g_esrc[j] = 0;
        g_einv[j] = 0.0f;
    }
    for (int j = i; j < N_PAD; j += stride) g_nperm[j] = -1;
    if (i < N_RELS) g_rel_cnt[i] = 0;
    if (i < N_NT) g_nt_cnt[i] = 0;
    if (i == 0) g_hist_done = 0;
    for (int j = i; j < N_RELS * D * D; j += stride) {
        int m = j >> 14, lin = j & 16383;
        int f = lin >> 7, d = lin & 127;
        g_WT[(size_t)m * D * D + pif(f) * D + phik(d)] =
            __uint_as_float(tf32r(We[(size_t)m * D * D + d * D + f]));
    }
    for (int j = i; j < N_NT * D * D; j += stride) {
        int m = j >> 14, lin = j & 16383;
        int f = lin >> 7, d = lin & 127;
        g_WnT[(size_t)m * D * D + f * D + d] =
            __uint_as_float(tf32r(Wn[(size_t)m * D * D + d * D + f]));
    }
}

/* ------------------------------ setup: histogram + last-block scan ------------------------------ */
__global__ void k_hist(const int* __restrict__ dst, const int* __restrict__ etypes,
                       const int* __restrict__ ntypes) {
    __shared__ int sh[N_RELS + N_NT];
    __shared__ int sLast;
    int tid = threadIdx.x;
    if (tid < N_RELS + N_NT) sh[tid] = 0;
    __syncthreads();
    int i = blockIdx.x * blockDim.x + tid;
    int stride = gridDim.x * blockDim.x;
    for (int e = i; e < N_EDGES; e += stride) {
        int t = etypes[e];
        atomicAdd(&sh[t], 1);
        atomicAdd(&g_counts[dst[e] * N_RELS + t], 1);
    }
    for (int n = i; n < N_NODES; n += stride) atomicAdd(&sh[N_RELS + ntypes[n]], 1);
    __syncthreads();
    if (tid < N_RELS) atomicAdd(&g_rel_cnt[tid], sh[tid]);
    else if (tid < N_RELS + N_NT) atomicAdd(&g_nt_cnt[tid - N_RELS], sh[tid]);

    /* last block performs the scan */
    __threadfence();
    __syncthreads();
    if (tid == 0) sLast = (atomicAdd(&g_hist_done, 1) == (int)gridDim.x - 1) ? 1 : 0;
    __syncthreads();
    if (sLast && tid == 0) {
        int off = 0;
        for (int t = 0; t < N_RELS; t++) {
            g_rel_cur[t] = off;
            off += ((g_rel_cnt[t] + TILE - 1) / TILE) * TILE;
        }
        g_ntiles[0] = off / TILE;
        off = 0;
        for (int t = 0; t < N_NT; t++) {
            g_nt_cur[t] = off;
            off += ((g_nt_cnt[t] + TILE - 1) / TILE) * TILE;
        }
        g_ntiles[1] = off / TILE;
    }
}

/* ------------------------------ setup: stable chunked scatter + per-edge meta ------------------------------ */
__global__ void k_scatter(const int* __restrict__ src, const int* __restrict__ dst,
                          const int* __restrict__ etypes, const int* __restrict__ ntypes) {
    __shared__ int s_cnt[N_RELS], s_base[N_RELS];
    const int CH = 2048;
    int tid = threadIdx.x;

    int nch = (N_EDGES + CH - 1) / CH;
    for (int ch = blockIdx.x; ch < nch; ch += gridDim.x) {
        int lo = ch * CH, hi = min(lo + CH, N_EDGES);
        if (tid < N_RELS) s_cnt[tid] = 0;
        __syncthreads();
        for (int e = lo + tid; e < hi; e += blockDim.x) atomicAdd(&s_cnt[etypes[e]], 1);
        __syncthreads();
        if (tid < N_RELS) {
            s_base[tid] = atomicAdd(&g_rel_cur[tid], s_cnt[tid]);
            s_cnt[tid] = 0;
        }
        __syncthreads();
        for (int e = lo + tid; e < hi; e += blockDim.x) {
            int t = etypes[e];
            int pos = s_base[t] + atomicAdd(&s_cnt[t], 1);
            int dn = dst[e];
            g_esrc[pos] = src[e];
            g_edst[pos] = dn;
            g_erel[pos] = t;
            g_einv[pos] = 1.0f / (float)g_counts[dn * N_RELS + t];
        }
        __syncthreads();
    }
    nch = (N_NODES + CH - 1) / CH;
    for (int ch = blockIdx.x; ch < nch; ch += gridDim.x) {
        int lo = ch * CH, hi = min(lo + CH, N_NODES);
        if (tid < N_NT) s_cnt[tid] = 0;
        __syncthreads();
        for (int n = lo + tid; n < hi; n += blockDim.x) atomicAdd(&s_cnt[ntypes[n]], 1);
        __syncthreads();
        if (tid < N_NT) {
            s_base[tid] = atomicAdd(&g_nt_cur[tid], s_cnt[tid]);
            s_cnt[tid] = 0;
        }
        __syncthreads();
        for (int n = lo + tid; n < hi; n += blockDim.x) {
            int t = ntypes[n];
            g_nperm[s_base[t] + atomicAdd(&s_cnt[t], 1)] = n;
        }
        __syncthreads();
    }
}

/* ------------------------------ edge GEMM: one tile per CTA, 512 thr, ONE barrier ------------------------------ */
/* Meta read straight from global (no smem staging hop); B copied by cp.async in
 * parallel with the A gather; single wait+barrier; v4 epilogue via pi-permuted B. */
__global__ __launch_bounds__(512, 1) void k_edge_v10(const float* __restrict__ b_edge) {
    if ((int)blockIdx.x >= g_ntiles[0]) return;

    extern __shared__ float smf[];
    float* sA = smf;                   /* [128][SROW], phi-interleaved k */
    float* sB = smf + 128 * SROW;      /* [128][SROW], phi-interleaved k, pi-permuted rows */

    __shared__ int sDst[TILE];
    __shared__ float sInv[TILE];
    __shared__ float sBias[TILE];

    const int tid = threadIdx.x;
    const int base = blockIdx.x * TILE;
    const int r = tid >> 2, q = tid & 3;

    const int rel = g_erel[base];          /* broadcast L2 load */

    /* B via cp.async: overlaps with the A gather below */
    {
        const float* Wr = g_WT + (size_t)rel * D * D;
#pragma unroll
        for (int i = 0; i < 8; i++) {
            int lin = tid + 512 * i;           /* 16B chunk id, 4096 total */
            int f = lin >> 5, wq = lin & 31;
            cpa16(smem_u32(sB + f * SROW + wq * 4), Wr + f * D + wq * 4);
        }
        asm volatile("cp.async.commit_group;" ::: "memory");
    }

    /* meta: straight from global into smem (epilogue reads it after the barrier) */
    if (q == 0) {
        sDst[r] = g_edst[base + r];
        sInv[r] = g_einv[base + r];
    }
    if (tid < TILE) sBias[tid] = b_edge[rel * D + tid];

    /* A gather, interleaving pairs (k, k+4) in registers */
    {
        int s = g_esrc[base + r];
        const float4* fp = (const float4*)(g_featsR + (size_t)s * D);
        float* ap = sA + r * SROW;
#pragma unroll
        for (int i = 0; i < 4; i++) {
            int g = q * 4 + i;
            float4 v1 = fp[g * 2];
            float4 v2 = fp[g * 2 + 1];
            float4 w1 = make_float4(v1.x, v2.x, v1.y, v2.y);
            float4 w2 = make_float4(v1.z, v2.z, v1.w, v2.w);
            *(float4*)(ap + g * 8) = w1;
            *(float4*)(ap + g * 8 + 4) = w2;
        }
    }

    asm volatile("cp.async.wait_group 0;" ::: "memory");
    __syncthreads();   /* the ONLY barrier */

    const int wid = tid >> 5, lane = tid & 31;
    const int wm = wid & 3, wn = wid >> 2;
    const int r_base = wm * 32, c_base = wn * 32;
    const int lq = lane >> 2, lr = lane & 3;

    float acc[2][4][4];
#pragma unroll
    for (int mt = 0; mt < 2; mt++)
#pragma unroll
        for (int nt = 0; nt < 4; nt++)
#pragma unroll
            for (int j = 0; j < 4; j++) acc[mt][nt][j] = 0.0f;

#pragma unroll 4
    for (int k0 = 0; k0 < 16; k0++) {
        const int kb = k0 * 8 + lr * 2;
        uint32_t a[2][4], bb[4][2];
#pragma unroll
        for (int mt = 0; mt < 2; mt++) {
            int row = r_base + mt * 16 + lq;
            float2 p0 = *(const float2*)(sA + row * SROW + kb);
            float2 p1 = *(const float2*)(sA + (row + 8) * SROW + kb);
            a[mt][0] = __float_as_uint(p0.x);
            a[mt][1] = __float_as_uint(p1.x);
            a[mt][2] = __float_as_uint(p0.y);
            a[mt][3] = __float_as_uint(p1.y);
        }
#pragma unroll
        for (int nt = 0; nt < 4; nt++) {
            int n = c_base + nt * 8 + lq;
            float2 pb = *(const float2*)(sB + n * SROW + kb);
            bb[nt][0] = __float_as_uint(pb.x);
            bb[nt][1] = __float_as_uint(pb.y);
        }
#pragma unroll
        for (int mt = 0; mt < 2; mt++)
#pragma unroll
            for (int nt = 0; nt < 4; nt++) mma8(acc[mt][nt], a[mt], bb[nt]);
    }

    /* epilogue: thread owns logical cols c_base + 16j + 4*lr .. +3, j=0,1 */
#pragma unroll
    for (int mt = 0; mt < 2; mt++)
#pragma unroll
        for (int h = 0; h < 2; h++) {
            int rr = r_base + mt * 16 + lq + h * 8;
            int dn = sDst[rr];
            if (dn < 0) continue;
            float inv = sInv[rr];
            float* gb = g_agg + (size_t)dn * D;
#pragma unroll
            for (int j = 0; j < 2; j++) {
                int Lc = c_base + j * 16 + 4 * lr;
                float4 bv = *(const float4*)(sBias + Lc);
                float x = (acc[mt][2 * j][h * 2 + 0] + bv.x) * inv;
                float y = (acc[mt][2 * j][h * 2 + 1] + bv.y) * inv;
                float z = (acc[mt][2 * j + 1][h * 2 + 0] + bv.z) * inv;
                float w = (acc[mt][2 * j + 1][h * 2 + 1] + bv.w) * inv;
                red4(gb + Lc, x, y, z, w);
            }
        }
}

/* ------------------------------ node GEMM + residual + relu ------------------------------ */
__global__ __launch_bounds__(256, 1) void k_node_mma(
    const float* __restrict__ b_node, const int* __restrict__ ntypes,
    float* __restrict__ out) {
    if ((int)blockIdx.x >= g_ntiles[1]) return;

    extern __shared__ float smf[];
    float* sA = smf;
    float* sB = smf + 128 * NSROW;
    const uint32_t* sAu = (const uint32_t*)sA;
    const uint32_t* sBu = (const uint32_t*)sB;

    __shared__ int sNode[TILE];
    __shared__ float sBias[TILE];
    __shared__ int sNt;

    const int tid = threadIdx.x, wid = tid >> 5, lane = tid & 31;
    const int base = blockIdx.x * TILE;

    if (tid < TILE) {
        int n = g_nperm[base + tid];
        sNode[tid] = n;
        if (tid == 0) sNt = ntypes[n];
    }
    __syncthreads();
    const int nt_ = sNt;
    if (tid < TILE) sBias[tid] = b_node[nt_ * D + tid];

    {
        int r = tid >> 1, half = tid & 1;
        int n = sNode[r];
        const float4* fp = (const float4*)(g_featsR + (size_t)(n >= 0 ? n : 0) * D) + half * 16;
        float* ap = sA + r * NSROW + half * 64;
#pragma unroll
        for (int i = 0; i < 16; i++) *(float4*)(ap + i * 4) = fp[i];
    }
    {
        const float* Wr = g_WnT + (size_t)nt_ * D * D;
#pragma unroll
        for (int i = 0; i < 16; i++) {
            int lin = tid + 256 * i;
            int f = lin >> 5, kq = lin & 31;
            *(float4*)(sB + f * NSROW + kq * 4) = *(const float4*)(Wr + f * D + kq * 4);
        }
    }
    __syncthreads();

    const int wm = wid & 1, wn = wid >> 1;
    const int r_base = wm * 64, c_base = wn * 32;
    const int lq = lane >> 2, lr = lane & 3;

    float acc[4][4][4];
#pragma unroll
    for (int mt = 0; mt < 4; mt++)
#pragma unroll
        for (int ntl = 0; ntl < 4; ntl++)
#pragma unroll
            for (int j = 0; j < 4; j++) acc[mt][ntl][j] = 0.0f;

#pragma unroll 4
    for (int k0 = 0; k0 < 16; k0++) {
        const int kk = k0 * 8 + lr;
        uint32_t a[4][4], b[4][2];
#pragma unroll
        for (int mt = 0; mt < 4; mt++) {
            int row = r_base + mt * 16 + lq;
            a[mt][0] = sAu[row * NSROW + kk];
            a[mt][1] = sAu[(row + 8) * NSROW + kk];
            a[mt][2] = sAu[row * NSROW + kk + 4];
            a[mt][3] = sAu[(row + 8) * NSROW + kk + 4];
        }
#pragma unroll
        for (int ntl = 0; ntl < 4; ntl++) {
            int n = c_base + ntl * 8 + lq;
            b[ntl][0] = sBu[n * NSROW + kk];
            b[ntl][1] = sBu[n * NSROW + kk + 4];
        }
#pragma unroll
        for (int mt = 0; mt < 4; mt++)
#pragma unroll
            for (int ntl = 0; ntl < 4; ntl++) mma8(acc[mt][ntl], a[mt], b[ntl]);
    }

#pragma unroll
    for (int mt = 0; mt < 4; mt++) {
        int row0 = r_base + mt * 16 + lq;
#pragma unroll
        for (int h = 0; h < 2; h++) {
            int rr = row0 + h * 8;
            int n = sNode[rr];
            if (n < 0) continue;
            const float* ab = g_agg + (size_t)n * D;
            float* ob = out + (size_t)n * D;
#pragma unroll
            for (int ntl = 0; ntl < 4; ntl++) {
                int col = c_base + ntl * 8 + lr * 2;
                float2 ag = *(const float2*)(ab + col);
                float2 o;
                o.x = fmaxf(acc[mt][ntl][h * 2 + 0] + sBias[col] + ag.x, 0.0f);
                o.y = fmaxf(acc[mt][ntl][h * 2 + 1] + sBias[col + 1] + ag.y, 0.0f);
                *(float2*)(ob + col) = o;
            }
        }
    }
}

/* ------------------------------ launch ------------------------------ */
extern "C" void kernel_launch(void* const* d_in, const int* in_sizes, int n_in,
                              void* d_out, int out_size) {
    const float* feats  = (const float*)d_in[0];
    const float* W_edge = (const float*)d_in[1];
    const float* b_edge = (const float*)d_in[2];
    const float* W_node = (const float*)d_in[3];
    const float* b_node = (const float*)d_in[4];
    const int* src    = (const int*)d_in[5];
    const int* dst    = (const int*)d_in[6];
    const int* ntypes = (const int*)d_in[7];
    const int* etypes = (const int*)d_in[8];
    float* out = (float*)d_out;
    (void)in_sizes; (void)n_in; (void)out_size;

    cudaFuncSetAttribute(k_edge_v10, cudaFuncAttributeMaxDynamicSharedMemorySize, EDGE_SMEM);
    cudaFuncSetAttribute(k_node_mma, cudaFuncAttributeMaxDynamicSharedMemorySize, NODE_SMEM);

    k_zero<<<2048, 256>>>(feats, W_edge, W_node);
    k_hist<<<640, 256>>>(dst, etypes, ntypes);
    k_scatter<<<320, 256>>>(src, dst, etypes, ntypes);
    k_edge_v10<<<EG, 512, EDGE_SMEM>>>(b_edge);
    k_node_mma<<<NG, 256, NODE_SMEM>>>(b_node, ntypes, out);
}

// round 11
// speedup vs baseline: 1.4920x; 1.1055x over previous
#include <cuda_runtime.h>
#include <cstdint>

#define N_NODES 50000
#define N_EDGES 640000
#define D 128
#define N_RELS 16
#define N_NT 8
#define TILE 128

#define EG (N_EDGES / TILE + N_RELS)
#define NG ((N_NODES + TILE - 1) / TILE + N_NT)
#define E_PAD (EG * TILE)
#define N_PAD (NG * TILE)

#define SROW 136                          /* padded row stride: bank-clean for LDS.64 */
#define TILE_BYTES (128 * SROW * 4)       /* 69632 */
#define EDGE_SMEM (3 * TILE_BYTES)        /* sB + sA0 + sA1 = 208896 B */
#define NODE_SMEM (2 * TILE_BYTES)
#define EDGE_GRID ((EG + 1) / 2)

/* ------------------------------ scratch ------------------------------ */
__device__ int   g_counts[N_NODES * N_RELS];
__device__ int   g_rel_cnt[N_RELS];
__device__ int   g_rel_cur[N_RELS];
__device__ int   g_nt_cnt[N_NT];
__device__ int   g_nt_cur[N_NT];
__device__ int   g_esrc[E_PAD];
__device__ int   g_edst[E_PAD];
__device__ float g_einv[E_PAD];
__device__ int   g_erel[E_PAD];
__device__ int   g_nperm[N_PAD];
__device__ float g_agg[N_NODES * D];
__device__ int   g_ntiles[2];
__device__ float g_WT[N_RELS * D * D];   /* W_edge^T, tf32, phi(k)-interleaved, pi(f)-row-permuted */
__device__ float g_WnT[N_NT * D * D];    /* W_node^T, tf32, phi(k)-interleaved */
__device__ float g_featsR[N_NODES * D];  /* feats, tf32-rounded, phi(k)-interleaved */
__device__ int   g_hist_done;

/* ------------------------------ helpers ------------------------------ */
__device__ __forceinline__ uint32_t tf32r(float x) {
    uint32_t r;
    asm("cvt.rna.tf32.f32 %0, %1;" : "=r"(r) : "f"(x));
    return r;
}
__device__ __forceinline__ uint32_t smem_u32(const void* p) {
    uint32_t a;
    asm("{ .reg .u64 t; cvta.to.shared.u64 t, %1; cvt.u32.u64 %0, t; }" : "=r"(a) : "l"(p));
    return a;
}
__device__ __forceinline__ void cpa16(uint32_t dstS, const void* src) {
    asm volatile("cp.async.cg.shared.global [%0], [%1], 16;" :: "r"(dstS), "l"(src));
}
__device__ __forceinline__ void mma8(float* c, const uint32_t* a, const uint32_t* b) {
    asm volatile(
        "mma.sync.aligned.m16n8k8.row.col.f32.tf32.tf32.f32 "
        "{%0,%1,%2,%3}, {%4,%5,%6,%7}, {%8,%9}, {%0,%1,%2,%3};"
        : "+f"(c[0]), "+f"(c[1]), "+f"(c[2]), "+f"(c[3])
        : "r"(a[0]), "r"(a[1]), "r"(a[2]), "r"(a[3]), "r"(b[0]), "r"(b[1]));
}
__device__ __forceinline__ void red4(float* p, float x, float y, float z, float w) {
    asm volatile("red.global.add.v4.f32 [%0], {%1,%2,%3,%4};"
                 :: "l"(p), "f"(x), "f"(y), "f"(z), "f"(w) : "memory");
}
/* pair-interleave: phi(k) = (k>>3)*8 + (k&3)*2 + ((k>>2)&1) */
__device__ __forceinline__ int phik(int k) {
    return ((k >> 3) << 3) + ((k & 3) << 1) + ((k >> 2) & 1);
}
/* row permutation for v4 epilogue: within 16-row group, f=4a+2b+c -> p=8b+2a+c */
__device__ __forceinline__ int pif(int f) {
    int a = (f >> 2) & 3, b = (f >> 1) & 1, c = f & 1;
    return (f & ~15) | (b << 3) | (a << 1) | c;
}

/* ------------------------------ setup: zero + round + transpose ------------------------------ */
__global__ void k_zero(const float* __restrict__ feats, const float* __restrict__ We,
                       const float* __restrict__ Wn) {
    int i = blockIdx.x * blockDim.x + threadIdx.x;
    int stride = gridDim.x * blockDim.x;
    for (int j = i; j < N_NODES * D; j += stride) {
        g_agg[j] = 0.0f;
        int n = j >> 7, d = j & 127;
        g_featsR[(n << 7) + phik(d)] = __uint_as_float(tf32r(feats[j]));
    }
    for (int j = i; j < N_NODES * N_RELS; j += stride) g_counts[j] = 0;
    for (int j = i; j < E_PAD; j += stride) {
        g_edst[j] = -1;
        g_esrc[j] = 0;
        g_einv[j] = 0.0f;
        g_erel[j] = 0;
    }
    for (int j = i; j < N_PAD; j += stride) g_nperm[j] = -1;
    if (i < N_RELS) g_rel_cnt[i] = 0;
    if (i < N_NT) g_nt_cnt[i] = 0;
    if (i == 0) g_hist_done = 0;
    for (int j = i; j < N_RELS * D * D; j += stride) {
        int m = j >> 14, lin = j & 16383;
        int f = lin >> 7, d = lin & 127;
        g_WT[(size_t)m * D * D + pif(f) * D + phik(d)] =
            __uint_as_float(tf32r(We[(size_t)m * D * D + d * D + f]));
    }
    for (int j = i; j < N_NT * D * D; j += stride) {
        int m = j >> 14, lin = j & 16383;
        int f = lin >> 7, d = lin & 127;
        g_WnT[(size_t)m * D * D + f * D + phik(d)] =
            __uint_as_float(tf32r(Wn[(size_t)m * D * D + d * D + f]));
    }
}

/* ------------------------------ setup: histogram + last-block scan ------------------------------ */
__global__ void k_hist(const int* __restrict__ dst, const int* __restrict__ etypes,
                       const int* __restrict__ ntypes) {
    __shared__ int sh[N_RELS + N_NT];
    __shared__ int sLast;
    int tid = threadIdx.x;
    if (tid < N_RELS + N_NT) sh[tid] = 0;
    __syncthreads();
    int i = blockIdx.x * blockDim.x + tid;
    int stride = gridDim.x * blockDim.x;
    for (int e = i; e < N_EDGES; e += stride) {
        int t = etypes[e];
        atomicAdd(&sh[t], 1);
        atomicAdd(&g_counts[dst[e] * N_RELS + t], 1);
    }
    for (int n = i; n < N_NODES; n += stride) atomicAdd(&sh[N_RELS + ntypes[n]], 1);
    __syncthreads();
    if (tid < N_RELS) atomicAdd(&g_rel_cnt[tid], sh[tid]);
    else if (tid < N_RELS + N_NT) atomicAdd(&g_nt_cnt[tid - N_RELS], sh[tid]);

    __threadfence();
    __syncthreads();
    if (tid == 0) sLast = (atomicAdd(&g_hist_done, 1) == (int)gridDim.x - 1) ? 1 : 0;
    __syncthreads();
    if (sLast && tid == 0) {
        int off = 0;
        for (int t = 0; t < N_RELS; t++) {
            g_rel_cur[t] = off;
            off += ((g_rel_cnt[t] + TILE - 1) / TILE) * TILE;
        }
        g_ntiles[0] = off / TILE;
        off = 0;
        for (int t = 0; t < N_NT; t++) {
            g_nt_cur[t] = off;
            off += ((g_nt_cnt[t] + TILE - 1) / TILE) * TILE;
        }
        g_ntiles[1] = off / TILE;
    }
}

/* ------------------------------ setup: stable chunked scatter + per-edge meta ------------------------------ */
__global__ void k_scatter(const int* __restrict__ src, const int* __restrict__ dst,
                          const int* __restrict__ etypes, const int* __restrict__ ntypes) {
    __shared__ int s_cnt[N_RELS], s_base[N_RELS];
    const int CH = 2048;
    int tid = threadIdx.x;

    int nch = (N_EDGES + CH - 1) / CH;
    for (int ch = blockIdx.x; ch < nch; ch += gridDim.x) {
        int lo = ch * CH, hi = min(lo + CH, N_EDGES);
        if (tid < N_RELS) s_cnt[tid] = 0;
        __syncthreads();
        for (int e = lo + tid; e < hi; e += blockDim.x) atomicAdd(&s_cnt[etypes[e]], 1);
        __syncthreads();
        if (tid < N_RELS) {
            s_base[tid] = atomicAdd(&g_rel_cur[tid], s_cnt[tid]);
            s_cnt[tid] = 0;
        }
        __syncthreads();
        for (int e = lo + tid; e < hi; e += blockDim.x) {
            int t = etypes[e];
            int pos = s_base[t] + atomicAdd(&s_cnt[t], 1);
            int dn = dst[e];
            g_esrc[pos] = src[e];
            g_edst[pos] = dn;
            g_erel[pos] = t;
            g_einv[pos] = 1.0f / (float)g_counts[dn * N_RELS + t];
        }
        __syncthreads();
    }
    nch = (N_NODES + CH - 1) / CH;
    for (int ch = blockIdx.x; ch < nch; ch += gridDim.x) {
        int lo = ch * CH, hi = min(lo + CH, N_NODES);
        if (tid < N_NT) s_cnt[tid] = 0;
        __syncthreads();
        for (int n = lo + tid; n < hi; n += blockDim.x) atomicAdd(&s_cnt[ntypes[n]], 1);
        __syncthreads();
        if (tid < N_NT) {
            s_base[tid] = atomicAdd(&g_nt_cur[tid], s_cnt[tid]);
            s_cnt[tid] = 0;
        }
        __syncthreads();
        for (int n = lo + tid; n < hi; n += blockDim.x) {
            int t = ntypes[n];
            g_nperm[s_base[t] + atomicAdd(&s_cnt[t], 1)] = n;
        }
        __syncthreads();
    }
}

/* ------------------------------ edge GEMM: TWO tiles per CTA, 512 thr ------------------------------ */
/* B + bias loaded once per pair (rel changes only at 16 bin boundaries).
 * A tiles stream in via cp.async (featsR is phi-interleaved so rows are raw byte copies).
 * Groups commit order: B, A0, A1; wait 1 -> B+A0 ready. One barrier per tile. */
__global__ __launch_bounds__(512, 1) void k_edge_v11(const float* __restrict__ b_edge) {
    const int ntiles = g_ntiles[0];
    const int t0 = 2 * blockIdx.x;
    if (t0 >= ntiles) return;
    const bool has2 = (t0 + 1) < ntiles;

    extern __shared__ float smf[];
    float* sB = smf;
    float* sA0 = smf + 128 * SROW;
    float* sA1 = smf + 2 * 128 * SROW;

    __shared__ int sDst[2][TILE];
    __shared__ float sInv[2][TILE];
    __shared__ float sBias[TILE];

    const int tid = threadIdx.x;
    const int base = t0 * TILE;
    const int r = tid >> 2, q = tid & 3;

    const int rel0 = g_erel[base];
    const int rel1 = has2 ? g_erel[base + TILE] : rel0;

    /* B via cp.async (group 0) */
    {
        const float* Wr = g_WT + (size_t)rel0 * D * D;
#pragma unroll
        for (int i = 0; i < 8; i++) {
            int lin = tid + 512 * i;
            int f = lin >> 5, wq = lin & 31;
            cpa16(smem_u32(sB + f * SROW + wq * 4), Wr + f * D + wq * 4);
        }
        asm volatile("cp.async.commit_group;" ::: "memory");
    }
    /* A0 via cp.async (group 1): raw row copy, featsR already phi-interleaved */
    {
        int s = g_esrc[base + r];
        const float* fp = g_featsR + ((size_t)s << 7) + q * 32;
        uint32_t ap = smem_u32(sA0 + r * SROW + q * 32);
#pragma unroll
        for (int c = 0; c < 8; c++) cpa16(ap + c * 16, fp + c * 4);
        asm volatile("cp.async.commit_group;" ::: "memory");
    }
    /* A1 via cp.async (group 2) */
    if (has2) {
        int s = g_esrc[base + TILE + r];
        const float* fp = g_featsR + ((size_t)s << 7) + q * 32;
        uint32_t ap = smem_u32(sA1 + r * SROW + q * 32);
#pragma unroll
        for (int c = 0; c < 8; c++) cpa16(ap + c * 16, fp + c * 4);
        asm volatile("cp.async.commit_group;" ::: "memory");
    }

    /* meta + bias (plain loads) */
    if (q == 0) {
        sDst[0][r] = g_edst[base + r];
        sInv[0][r] = g_einv[base + r];
    } else if (q == 1 && has2) {
        sDst[1][r] = g_edst[base + TILE + r];
        sInv[1][r] = g_einv[base + TILE + r];
    }
    if (tid < TILE) sBias[tid] = b_edge[rel0 * D + tid];

    if (has2) asm volatile("cp.async.wait_group 1;" ::: "memory");
    else      asm volatile("cp.async.wait_group 0;" ::: "memory");
    __syncthreads();

    const int wid = tid >> 5, lane = tid & 31;
    const int wm = wid & 3, wn = wid >> 2;
    const int r_base = wm * 32, c_base = wn * 32;
    const int lq = lane >> 2, lr = lane & 3;

    /* ---------------- tile 0 ---------------- */
    {
        float acc[2][4][4];
#pragma unroll
        for (int mt = 0; mt < 2; mt++)
#pragma unroll
            for (int nt = 0; nt < 4; nt++)
#pragma unroll
                for (int j = 0; j < 4; j++) acc[mt][nt][j] = 0.0f;

#pragma unroll 4
        for (int k0 = 0; k0 < 16; k0++) {
            const int kb = k0 * 8 + lr * 2;
            uint32_t a[2][4], bb[4][2];
#pragma unroll
            for (int mt = 0; mt < 2; mt++) {
                int row = r_base + mt * 16 + lq;
                float2 p0 = *(const float2*)(sA0 + row * SROW + kb);
                float2 p1 = *(const float2*)(sA0 + (row + 8) * SROW + kb);
                a[mt][0] = __float_as_uint(p0.x);
                a[mt][1] = __float_as_uint(p1.x);
                a[mt][2] = __float_as_uint(p0.y);
                a[mt][3] = __float_as_uint(p1.y);
            }
#pragma unroll
            for (int nt = 0; nt < 4; nt++) {
                int n = c_base + nt * 8 + lq;
                float2 pb = *(const float2*)(sB + n * SROW + kb);
                bb[nt][0] = __float_as_uint(pb.x);
                bb[nt][1] = __float_as_uint(pb.y);
            }
#pragma unroll
            for (int mt = 0; mt < 2; mt++)
#pragma unroll
                for (int nt = 0; nt < 4; nt++) mma8(acc[mt][nt], a[mt], bb[nt]);
        }

#pragma unroll
        for (int mt = 0; mt < 2; mt++)
#pragma unroll
            for (int h = 0; h < 2; h++) {
                int rr = r_base + mt * 16 + lq + h * 8;
                int dn = sDst[0][rr];
                if (dn < 0) continue;
                float inv = sInv[0][rr];
                float* gb = g_agg + (size_t)dn * D;
#pragma unroll
                for (int j = 0; j < 2; j++) {
                    int Lc = c_base + j * 16 + 4 * lr;
                    float4 bv = *(const float4*)(sBias + Lc);
                    float x = (acc[mt][2 * j][h * 2 + 0] + bv.x) * inv;
                    float y = (acc[mt][2 * j][h * 2 + 1] + bv.y) * inv;
                    float z = (acc[mt][2 * j + 1][h * 2 + 0] + bv.z) * inv;
                    float w = (acc[mt][2 * j + 1][h * 2 + 1] + bv.w) * inv;
                    red4(gb + Lc, x, y, z, w);
                }
            }
    }

    if (!has2) return;

    asm volatile("cp.async.wait_group 0;" ::: "memory");
    __syncthreads();   /* A1 visible to all; all reads of sB done */

    if (rel1 != rel0) {   /* rare: relation boundary inside the pair */
        const float* Wr = g_WT + (size_t)rel1 * D * D;
#pragma unroll
        for (int i = 0; i < 8; i++) {
            int lin = tid + 512 * i;
            int f = lin >> 5, wq = lin & 31;
            *(float4*)(sB + f * SROW + wq * 4) = *(const float4*)(Wr + f * D + wq * 4);
        }
        if (tid < TILE) sBias[tid] = b_edge[rel1 * D + tid];
        __syncthreads();
    }

    /* ---------------- tile 1 ---------------- */
    {
        float acc[2][4][4];
#pragma unroll
        for (int mt = 0; mt < 2; mt++)
#pragma unroll
            for (int nt = 0; nt < 4; nt++)
#pragma unroll
                for (int j = 0; j < 4; j++) acc[mt][nt][j] = 0.0f;

#pragma unroll 4
        for (int k0 = 0; k0 < 16; k0++) {
            const int kb = k0 * 8 + lr * 2;
            uint32_t a[2][4], bb[4][2];
#pragma unroll
            for (int mt = 0; mt < 2; mt++) {
                int row = r_base + mt * 16 + lq;
                float2 p0 = *(const float2*)(sA1 + row * SROW + kb);
                float2 p1 = *(const float2*)(sA1 + (row + 8) * SROW + kb);
                a[mt][0] = __float_as_uint(p0.x);
                a[mt][1] = __float_as_uint(p1.x);
                a[mt][2] = __float_as_uint(p0.y);
                a[mt][3] = __float_as_uint(p1.y);
            }
#pragma unroll
            for (int nt = 0; nt < 4; nt++) {
                int n = c_base + nt * 8 + lq;
                float2 pb = *(const float2*)(sB + n * SROW + kb);
                bb[nt][0] = __float_as_uint(pb.x);
                bb[nt][1] = __float_as_uint(pb.y);
            }
#pragma unroll
            for (int mt = 0; mt < 2; mt++)
#pragma unroll
                for (int nt = 0; nt < 4; nt++) mma8(acc[mt][nt], a[mt], bb[nt]);
        }

#pragma unroll
        for (int mt = 0; mt < 2; mt++)
#pragma unroll
            for (int h = 0; h < 2; h++) {
                int rr = r_base + mt * 16 + lq + h * 8;
                int dn = sDst[1][rr];
                if (dn < 0) continue;
                float inv = sInv[1][rr];
                float* gb = g_agg + (size_t)dn * D;
#pragma unroll
                for (int j = 0; j < 2; j++) {
                    int Lc = c_base + j * 16 + 4 * lr;
                    float4 bv = *(const float4*)(sBias + Lc);
                    float x = (acc[mt][2 * j][h * 2 + 0] + bv.x) * inv;
                    float y = (acc[mt][2 * j][h * 2 + 1] + bv.y) * inv;
                    float z = (acc[mt][2 * j + 1][h * 2 + 0] + bv.z) * inv;
                    float w = (acc[mt][2 * j + 1][h * 2 + 1] + bv.w) * inv;
                    red4(gb + Lc, x, y, z, w);
                }
            }
    }
}

/* ------------------------------ node GEMM + residual + relu (phi layout) ------------------------------ */
__global__ __launch_bounds__(256, 1) void k_node_mma(
    const float* __restrict__ b_node, const int* __restrict__ ntypes,
    float* __restrict__ out) {
    if ((int)blockIdx.x >= g_ntiles[1]) return;

    extern __shared__ float smf[];
    float* sA = smf;
    float* sB = smf + 128 * SROW;

    __shared__ int sNode[TILE];
    __shared__ float sBias[TILE];
    __shared__ int sNt;

    const int tid = threadIdx.x, wid = tid >> 5, lane = tid & 31;
    const int base = blockIdx.x * TILE;

    if (tid < TILE) {
        int n = g_nperm[base + tid];
        sNode[tid] = n;
        if (tid == 0) sNt = ntypes[n];
    }
    __syncthreads();
    const int nt_ = sNt;
    if (tid < TILE) sBias[tid] = b_node[nt_ * D + tid];

    {
        int r = tid >> 1, half = tid & 1;
        int n = sNode[r];
        const float4* fp = (const float4*)(g_featsR + ((size_t)(n >= 0 ? n : 0) << 7)) + half * 16;
        float* ap = sA + r * SROW + half * 64;
#pragma unroll
        for (int i = 0; i < 16; i++) *(float4*)(ap + i * 4) = fp[i];
    }
    {
        const float* Wr = g_WnT + (size_t)nt_ * D * D;
#pragma unroll
        for (int i = 0; i < 16; i++) {
            int lin = tid + 256 * i;
            int f = lin >> 5, kq = lin & 31;
            *(float4*)(sB + f * SROW + kq * 4) = *(const float4*)(Wr + f * D + kq * 4);
        }
    }
    __syncthreads();

    const int wm = wid & 1, wn = wid >> 1;
    const int r_base = wm * 64, c_base = wn * 32;
    const int lq = lane >> 2, lr = lane & 3;

    float acc[4][4][4];
#pragma unroll
    for (int mt = 0; mt < 4; mt++)
#pragma unroll
        for (int ntl = 0; ntl < 4; ntl++)
#pragma unroll
            for (int j = 0; j < 4; j++) acc[mt][ntl][j] = 0.0f;

#pragma unroll 4
    for (int k0 = 0; k0 < 16; k0++) {
        const int kb = k0 * 8 + lr * 2;
        uint32_t a[4][4], b[4][2];
#pragma unroll
        for (int mt = 0; mt < 4; mt++) {
            int row = r_base + mt * 16 + lq;
            float2 p0 = *(const float2*)(sA + row * SROW + kb);
            float2 p1 = *(const float2*)(sA + (row + 8) * SROW + kb);
            a[mt][0] = __float_as_uint(p0.x);
            a[mt][1] = __float_as_uint(p1.x);
            a[mt][2] = __float_as_uint(p0.y);
            a[mt][3] = __float_as_uint(p1.y);
        }
#pragma unroll
        for (int ntl = 0; ntl < 4; ntl++) {
            int n = c_base + ntl * 8 + lq;
            float2 pb = *(const float2*)(sB + n * SROW + kb);
            b[ntl][0] = __float_as_uint(pb.x);
            b[ntl][1] = __float_as_uint(pb.y);
        }
#pragma unroll
        for (int mt = 0; mt < 4; mt++)
#pragma unroll
            for (int ntl = 0; ntl < 4; ntl++) mma8(acc[mt][ntl], a[mt], b[ntl]);
    }

#pragma unroll
    for (int mt = 0; mt < 4; mt++) {
        int row0 = r_base + mt * 16 + lq;
#pragma unroll
        for (int h = 0; h < 2; h++) {
            int rr = row0 + h * 8;
            int n = sNode[rr];
            if (n < 0) continue;
            const float* ab = g_agg + (size_t)n * D;
            float* ob = out + (size_t)n * D;
#pragma unroll
            for (int ntl = 0; ntl < 4; ntl++) {
                int col = c_base + ntl * 8 + lr * 2;
                float2 ag = *(const float2*)(ab + col);
                float2 o;
                o.x = fmaxf(acc[mt][ntl][h * 2 + 0] + sBias[col] + ag.x, 0.0f);
                o.y = fmaxf(acc[mt][ntl][h * 2 + 1] + sBias[col + 1] + ag.y, 0.0f);
                *(float2*)(ob + col) = o;
            }
        }
    }
}

/* ------------------------------ launch ------------------------------ */
extern "C" void kernel_launch(void* const* d_in, const int* in_sizes, int n_in,
                              void* d_out, int out_size) {
    const float* feats  = (const float*)d_in[0];
    const float* W_edge = (const float*)d_in[1];
    const float* b_edge = (const float*)d_in[2];
    const float* W_node = (const float*)d_in[3];
    const float* b_node = (const float*)d_in[4];
    const int* src    = (const int*)d_in[5];
    const int* dst    = (const int*)d_in[6];
    const int* ntypes = (const int*)d_in[7];
    const int* etypes = (const int*)d_in[8];
    float* out = (float*)d_out;
    (void)in_sizes; (void)n_in; (void)out_size;

    cudaFuncSetAttribute(k_edge_v11, cudaFuncAttributeMaxDynamicSharedMemorySize, EDGE_SMEM);
    cudaFuncSetAttribute(k_node_mma, cudaFuncAttributeMaxDynamicSharedMemorySize, NODE_SMEM);

    k_zero<<<2048, 256>>>(feats, W_edge, W_node);
    k_hist<<<640, 256>>>(dst, etypes, ntypes);
    k_scatter<<<320, 256>>>(src, dst, etypes, ntypes);
    k_edge_v11<<<EDGE_GRID, 512, EDGE_SMEM>>>(b_edge);
    k_node_mma<<<NG, 256, NODE_SMEM>>>(b_node, ntypes, out);
}

// round 12
// speedup vs baseline: 1.5309x; 1.0261x over previous
#include <cuda_runtime.h>
#include <cstdint>

#define N_NODES 50000
#define N_EDGES 640000
#define D 128
#define N_RELS 16
#define N_NT 8
#define TILE 128

#define EG (N_EDGES / TILE + 2 * N_RELS)  /* bins padded to 2-tile multiples: 5032 */
#define NG ((N_NODES + TILE - 1) / TILE + N_NT)
#define E_PAD (EG * TILE)
#define N_PAD (NG * TILE)

#define SROW 136                          /* padded row stride: bank-clean for LDS.64 */
#define TILE_BYTES (128 * SROW * 4)       /* 69632 */
#define EDGE_SMEM (3 * TILE_BYTES)        /* sB + sA0 + sA1 = 208896 B */
#define NODE_SMEM (2 * TILE_BYTES)
#define EDGE_GRID (EG / 2)                /* 2516; pairs are rel-uniform by construction */

/* ------------------------------ scratch ------------------------------ */
__device__ int   g_counts[N_NODES * N_RELS];
__device__ int   g_rel_cnt[N_RELS];
__device__ int   g_rel_cur[N_RELS];
__device__ int   g_nt_cnt[N_NT];
__device__ int   g_nt_cur[N_NT];
__device__ int   g_esrc[E_PAD];
__device__ int   g_edst[E_PAD];
__device__ float g_einv[E_PAD];
__device__ int   g_erel[E_PAD];
__device__ int   g_nperm[N_PAD];
__device__ float g_agg[N_NODES * D];
__device__ int   g_ntiles[2];
__device__ float g_WT[N_RELS * D * D];   /* W_edge^T, tf32, phi(k)-interleaved, pi(f)-row-permuted */
__device__ float g_WnT[N_NT * D * D];    /* W_node^T, tf32, phi(k)-interleaved */
__device__ float g_featsR[N_NODES * D];  /* feats, tf32-rounded, phi(k)-interleaved */
__device__ int   g_hist_done;

/* ------------------------------ helpers ------------------------------ */
__device__ __forceinline__ uint32_t tf32r(float x) {
    uint32_t r;
    asm("cvt.rna.tf32.f32 %0, %1;" : "=r"(r) : "f"(x));
    return r;
}
__device__ __forceinline__ uint32_t smem_u32(const void* p) {
    uint32_t a;
    asm("{ .reg .u64 t; cvta.to.shared.u64 t, %1; cvt.u32.u64 %0, t; }" : "=r"(a) : "l"(p));
    return a;
}
__device__ __forceinline__ void cpa16(uint32_t dstS, const void* src) {
    asm volatile("cp.async.cg.shared.global [%0], [%1], 16;" :: "r"(dstS), "l"(src));
}
__device__ __forceinline__ void mma8(float* c, const uint32_t* a, const uint32_t* b) {
    asm volatile(
        "mma.sync.aligned.m16n8k8.row.col.f32.tf32.tf32.f32 "
        "{%0,%1,%2,%3}, {%4,%5,%6,%7}, {%8,%9}, {%0,%1,%2,%3};"
        : "+f"(c[0]), "+f"(c[1]), "+f"(c[2]), "+f"(c[3])
        : "r"(a[0]), "r"(a[1]), "r"(a[2]), "r"(a[3]), "r"(b[0]), "r"(b[1]));
}
__device__ __forceinline__ void red4(float* p, float x, float y, float z, float w) {
    asm volatile("red.global.add.v4.f32 [%0], {%1,%2,%3,%4};"
                 :: "l"(p), "f"(x), "f"(y), "f"(z), "f"(w) : "memory");
}
/* pair-interleave: phi(k) = (k>>3)*8 + (k&3)*2 + ((k>>2)&1) */
__device__ __forceinline__ int phik(int k) {
    return ((k >> 3) << 3) + ((k & 3) << 1) + ((k >> 2) & 1);
}
/* row permutation for v4 epilogue: within 16-row group, f=4a+2b+c -> p=8b+2a+c */
__device__ __forceinline__ int pif(int f) {
    int a = (f >> 2) & 3, b = (f >> 1) & 1, c = f & 1;
    return (f & ~15) | (b << 3) | (a << 1) | c;
}

/* ------------------------------ setup: zero + round + transpose ------------------------------ */
__global__ void k_zero(const float* __restrict__ feats, const float* __restrict__ We,
                       const float* __restrict__ Wn) {
    int i = blockIdx.x * blockDim.x + threadIdx.x;
    int stride = gridDim.x * blockDim.x;
    for (int j = i; j < N_NODES * D; j += stride) {
        g_agg[j] = 0.0f;
        int n = j >> 7, d = j & 127;
        g_featsR[(n << 7) + phik(d)] = __uint_as_float(tf32r(feats[j]));
    }
    for (int j = i; j < N_NODES * N_RELS; j += stride) g_counts[j] = 0;
    for (int j = i; j < E_PAD; j += stride) {
        g_edst[j] = -1;
        g_esrc[j] = 0;
        g_einv[j] = 0.0f;
        g_erel[j] = 0;
    }
    for (int j = i; j < N_PAD; j += stride) g_nperm[j] = -1;
    if (i < N_RELS) g_rel_cnt[i] = 0;
    if (i < N_NT) g_nt_cnt[i] = 0;
    if (i == 0) g_hist_done = 0;
    for (int j = i; j < N_RELS * D * D; j += stride) {
        int m = j >> 14, lin = j & 16383;
        int f = lin >> 7, d = lin & 127;
        g_WT[(size_t)m * D * D + pif(f) * D + phik(d)] =
            __uint_as_float(tf32r(We[(size_t)m * D * D + d * D + f]));
    }
    for (int j = i; j < N_NT * D * D; j += stride) {
        int m = j >> 14, lin = j & 16383;
        int f = lin >> 7, d = lin & 127;
        g_WnT[(size_t)m * D * D + f * D + phik(d)] =
            __uint_as_float(tf32r(Wn[(size_t)m * D * D + d * D + f]));
    }
}

/* ------------------------------ setup: histogram + last-block scan ------------------------------ */
__global__ void k_hist(const int* __restrict__ dst, const int* __restrict__ etypes,
                       const int* __restrict__ ntypes) {
    __shared__ int sh[N_RELS + N_NT];
    __shared__ int sLast;
    int tid = threadIdx.x;
    if (tid < N_RELS + N_NT) sh[tid] = 0;
    __syncthreads();
    int i = blockIdx.x * blockDim.x + tid;
    int stride = gridDim.x * blockDim.x;
    for (int e = i; e < N_EDGES; e += stride) {
        int t = etypes[e];
        atomicAdd(&sh[t], 1);
        atomicAdd(&g_counts[dst[e] * N_RELS + t], 1);
    }
    for (int n = i; n < N_NODES; n += stride) atomicAdd(&sh[N_RELS + ntypes[n]], 1);
    __syncthreads();
    if (tid < N_RELS) atomicAdd(&g_rel_cnt[tid], sh[tid]);
    else if (tid < N_RELS + N_NT) atomicAdd(&g_nt_cnt[tid - N_RELS], sh[tid]);

    __threadfence();
    __syncthreads();
    if (tid == 0) sLast = (atomicAdd(&g_hist_done, 1) == (int)gridDim.x - 1) ? 1 : 0;
    __syncthreads();
    if (sLast && tid == 0) {
        int off = 0;
        for (int t = 0; t < N_RELS; t++) {
            g_rel_cur[t] = off;
            off += ((g_rel_cnt[t] + 2 * TILE - 1) / (2 * TILE)) * (2 * TILE); /* 256-aligned bins */
        }
        g_ntiles[0] = off / TILE;   /* even by construction */
        off = 0;
        for (int t = 0; t < N_NT; t++) {
            g_nt_cur[t] = off;
            off += ((g_nt_cnt[t] + TILE - 1) / TILE) * TILE;
        }
        g_ntiles[1] = off / TILE;
    }
}

/* ------------------------------ setup: stable chunked scatter + per-edge meta ------------------------------ */
__global__ void k_scatter(const int* __restrict__ src, const int* __restrict__ dst,
                          const int* __restrict__ etypes, const int* __restrict__ ntypes) {
    __shared__ int s_cnt[N_RELS], s_base[N_RELS];
    const int CH = 2048;
    int tid = threadIdx.x;

    int nch = (N_EDGES + CH - 1) / CH;
    for (int ch = blockIdx.x; ch < nch; ch += gridDim.x) {
        int lo = ch * CH, hi = min(lo + CH, N_EDGES);
        if (tid < N_RELS) s_cnt[tid] = 0;
        __syncthreads();
        for (int e = lo + tid; e < hi; e += blockDim.x) atomicAdd(&s_cnt[etypes[e]], 1);
        __syncthreads();
        if (tid < N_RELS) {
            s_base[tid] = atomicAdd(&g_rel_cur[tid], s_cnt[tid]);
            s_cnt[tid] = 0;
        }
        __syncthreads();
        for (int e = lo + tid; e < hi; e += blockDim.x) {
            int t = etypes[e];
            int pos = s_base[t] + atomicAdd(&s_cnt[t], 1);
            int dn = dst[e];
            g_esrc[pos] = src[e];
            g_edst[pos] = dn;
            g_erel[pos] = t;
            g_einv[pos] = 1.0f / (float)g_counts[dn * N_RELS + t];
        }
        __syncthreads();
    }
    nch = (N_NODES + CH - 1) / CH;
    for (int ch = blockIdx.x; ch < nch; ch += gridDim.x) {
        int lo = ch * CH, hi = min(lo + CH, N_NODES);
        if (tid < N_NT) s_cnt[tid] = 0;
        __syncthreads();
        for (int n = lo + tid; n < hi; n += blockDim.x) atomicAdd(&s_cnt[ntypes[n]], 1);
        __syncthreads();
        if (tid < N_NT) {
            s_base[tid] = atomicAdd(&g_nt_cur[tid], s_cnt[tid]);
            s_cnt[tid] = 0;
        }
        __syncthreads();
        for (int n = lo + tid; n < hi; n += blockDim.x) {
            int t = ntypes[n];
            g_nperm[s_base[t] + atomicAdd(&s_cnt[t], 1)] = n;
        }
        __syncthreads();
    }
}

/* ------------------------------ edge GEMM: fused 256x128 pair per CTA, 512 thr ------------------------------ */
/* Bins 256-aligned => both tiles share rel. 16 warps as 4m x 4n, 64x32 warp tiles
 * (12 LDS.64 per 16 HMMA). Single mainloop, single barrier, v4 reg-direct epilogue. */
__global__ __launch_bounds__(512, 1) void k_edge_v12(const float* __restrict__ b_edge) {
    const int t0 = 2 * blockIdx.x;
    if (t0 >= g_ntiles[0]) return;

    extern __shared__ float smf[];
    float* sB = smf;
    float* sA0 = smf + 128 * SROW;

    __shared__ int sDst[2 * TILE];
    __shared__ float sInv[2 * TILE];
    __shared__ float sBias[TILE];

    const int tid = threadIdx.x;
    const int base = t0 * TILE;
    const int r = tid >> 2, q = tid & 3;

    const int rel = g_erel[base];

    /* B via cp.async */
    {
        const float* Wr = g_WT + (size_t)rel * D * D;
#pragma unroll
        for (int i = 0; i < 8; i++) {
            int lin = tid + 512 * i;
            int f = lin >> 5, wq = lin & 31;
            cpa16(smem_u32(sB + f * SROW + wq * 4), Wr + f * D + wq * 4);
        }
    }
    /* A0 + A1 via cp.async: raw row copies (featsR phi-interleaved) */
#pragma unroll
    for (int t = 0; t < 2; t++) {
        int s = g_esrc[base + t * TILE + r];
        const float* fp = g_featsR + ((size_t)s << 7) + q * 32;
        uint32_t ap = smem_u32(sA0 + t * 128 * SROW + r * SROW + q * 32);
#pragma unroll
        for (int c = 0; c < 8; c++) cpa16(ap + c * 16, fp + c * 4);
    }
    asm volatile("cp.async.commit_group;" ::: "memory");

    /* meta + bias (plain loads) */
    if (q < 2) {
        sDst[q * TILE + r] = g_edst[base + q * TILE + r];
        sInv[q * TILE + r] = g_einv[base + q * TILE + r];
    }
    if (tid < TILE) sBias[tid] = b_edge[rel * D + tid];

    asm volatile("cp.async.wait_group 0;" ::: "memory");
    __syncthreads();   /* the ONLY barrier */

    const int wid = tid >> 5, lane = tid & 31;
    const int wm = wid & 3, wn = wid >> 2;
    const int c_base = wn * 32;
    const int lq = lane >> 2, lr = lane & 3;
    /* warp's 64 rows: global rows wm*64 .. wm*64+63 of the fused 256-row tile */
    float* sAw = sA0 + (wm >> 1) * 128 * SROW + (wm & 1) * 64 * SROW;

    float acc[4][4][4];
#pragma unroll
    for (int mt = 0; mt < 4; mt++)
#pragma unroll
        for (int nt = 0; nt < 4; nt++)
#pragma unroll
            for (int j = 0; j < 4; j++) acc[mt][nt][j] = 0.0f;

#pragma unroll 2
    for (int k0 = 0; k0 < 16; k0++) {
        const int kb = k0 * 8 + lr * 2;
        uint32_t a[4][4], bb[4][2];
#pragma unroll
        for (int mt = 0; mt < 4; mt++) {
            int row = mt * 16 + lq;
            float2 p0 = *(const float2*)(sAw + row * SROW + kb);
            float2 p1 = *(const float2*)(sAw + (row + 8) * SROW + kb);
            a[mt][0] = __float_as_uint(p0.x);
            a[mt][1] = __float_as_uint(p1.x);
            a[mt][2] = __float_as_uint(p0.y);
            a[mt][3] = __float_as_uint(p1.y);
        }
#pragma unroll
        for (int nt = 0; nt < 4; nt++) {
            int n = c_base + nt * 8 + lq;
            float2 pb = *(const float2*)(sB + n * SROW + kb);
            bb[nt][0] = __float_as_uint(pb.x);
            bb[nt][1] = __float_as_uint(pb.y);
        }
#pragma unroll
        for (int mt = 0; mt < 4; mt++)
#pragma unroll
            for (int nt = 0; nt < 4; nt++) mma8(acc[mt][nt], a[mt], bb[nt]);
    }

    /* epilogue: fused row id = wm*64 + mt*16 + lq + h*8 in [0,256) */
#pragma unroll
    for (int mt = 0; mt < 4; mt++)
#pragma unroll
        for (int h = 0; h < 2; h++) {
            int rr = wm * 64 + mt * 16 + lq + h * 8;
            int dn = sDst[rr];
            if (dn < 0) continue;
            float inv = sInv[rr];
            float* gb = g_agg + (size_t)dn * D;
#pragma unroll
            for (int j = 0; j < 2; j++) {
                int Lc = c_base + j * 16 + 4 * lr;
                float4 bv = *(const float4*)(sBias + Lc);
                float x = (acc[mt][2 * j][h * 2 + 0] + bv.x) * inv;
                float y = (acc[mt][2 * j][h * 2 + 1] + bv.y) * inv;
                float z = (acc[mt][2 * j + 1][h * 2 + 0] + bv.z) * inv;
                float w = (acc[mt][2 * j + 1][h * 2 + 1] + bv.w) * inv;
                red4(gb + Lc, x, y, z, w);
            }
        }
}

/* ------------------------------ node GEMM + residual + relu (phi layout) ------------------------------ */
__global__ __launch_bounds__(256, 1) void k_node_mma(
    const float* __restrict__ b_node, const int* __restrict__ ntypes,
    float* __restrict__ out) {
    if ((int)blockIdx.x >= g_ntiles[1]) return;

    extern __shared__ float smf[];
    float* sA = smf;
    float* sB = smf + 128 * SROW;

    __shared__ int sNode[TILE];
    __shared__ float sBias[TILE];
    __shared__ int sNt;

    const int tid = threadIdx.x, wid = tid >> 5, lane = tid & 31;
    const int base = blockIdx.x * TILE;

    if (tid < TILE) {
        int n = g_nperm[base + tid];
        sNode[tid] = n;
        if (tid == 0) sNt = ntypes[n];
    }
    __syncthreads();
    const int nt_ = sNt;
    if (tid < TILE) sBias[tid] = b_node[nt_ * D + tid];

    {
        int r = tid >> 1, half = tid & 1;
        int n = sNode[r];
        const float4* fp = (const float4*)(g_featsR + ((size_t)(n >= 0 ? n : 0) << 7)) + half * 16;
        float* ap = sA + r * SROW + half * 64;
#pragma unroll
        for (int i = 0; i < 16; i++) *(float4*)(ap + i * 4) = fp[i];
    }
    {
        const float* Wr = g_WnT + (size_t)nt_ * D * D;
#pragma unroll
        for (int i = 0; i < 16; i++) {
            int lin = tid + 256 * i;
            int f = lin >> 5, kq = lin & 31;
            *(float4*)(sB + f * SROW + kq * 4) = *(const float4*)(Wr + f * D + kq * 4);
        }
    }
    __syncthreads();

    const int wm = wid & 1, wn = wid >> 1;
    const int r_base = wm * 64, c_base = wn * 32;
    const int lq = lane >> 2, lr = lane & 3;

    float acc[4][4][4];
#pragma unroll
    for (int mt = 0; mt < 4; mt++)
#pragma unroll
        for (int ntl = 0; ntl < 4; ntl++)
#pragma unroll
            for (int j = 0; j < 4; j++) acc[mt][ntl][j] = 0.0f;

#pragma unroll 4
    for (int k0 = 0; k0 < 16; k0++) {
        const int kb = k0 * 8 + lr * 2;
        uint32_t a[4][4], b[4][2];
#pragma unroll
        for (int mt = 0; mt < 4; mt++) {
            int row = r_base + mt * 16 + lq;
            float2 p0 = *(const float2*)(sA + row * SROW + kb);
            float2 p1 = *(const float2*)(sA + (row + 8) * SROW + kb);
            a[mt][0] = __float_as_uint(p0.x);
            a[mt][1] = __float_as_uint(p1.x);
            a[mt][2] = __float_as_uint(p0.y);
            a[mt][3] = __float_as_uint(p1.y);
        }
#pragma unroll
        for (int ntl = 0; ntl < 4; ntl++) {
            int n = c_base + ntl * 8 + lq;
            float2 pb = *(const float2*)(sB + n * SROW + kb);
            b[ntl][0] = __float_as_uint(pb.x);
            b[ntl][1] = __float_as_uint(pb.y);
        }
#pragma unroll
        for (int mt = 0; mt < 4; mt++)
#pragma unroll
            for (int ntl = 0; ntl < 4; ntl++) mma8(acc[mt][ntl], a[mt], b[ntl]);
    }

#pragma unroll
    for (int mt = 0; mt < 4; mt++) {
        int row0 = r_base + mt * 16 + lq;
#pragma unroll
        for (int h = 0; h < 2; h++) {
            int rr = row0 + h * 8;
            int n = sNode[rr];
            if (n < 0) continue;
            const float* ab = g_agg + (size_t)n * D;
            float* ob = out + (size_t)n * D;
#pragma unroll
            for (int ntl = 0; ntl < 4; ntl++) {
                int col = c_base + ntl * 8 + lr * 2;
                float2 ag = *(const float2*)(ab + col);
                float2 o;
                o.x = fmaxf(acc[mt][ntl][h * 2 + 0] + sBias[col] + ag.x, 0.0f);
                o.y = fmaxf(acc[mt][ntl][h * 2 + 1] + sBias[col + 1] + ag.y, 0.0f);
                *(float2*)(ob + col) = o;
            }
        }
    }
}

/* ------------------------------ launch ------------------------------ */
extern "C" void kernel_launch(void* const* d_in, const int* in_sizes, int n_in,
                              void* d_out, int out_size) {
    const float* feats  = (const float*)d_in[0];
    const float* W_edge = (const float*)d_in[1];
    const float* b_edge = (const float*)d_in[2];
    const float* W_node = (const float*)d_in[3];
    const float* b_node = (const float*)d_in[4];
    const int* src    = (const int*)d_in[5];
    const int* dst    = (const int*)d_in[6];
    const int* ntypes = (const int*)d_in[7];
    const int* etypes = (const int*)d_in[8];
    float* out = (float*)d_out;
    (void)in_sizes; (void)n_in; (void)out_size;

    cudaFuncSetAttribute(k_edge_v12, cudaFuncAttributeMaxDynamicSharedMemorySize, EDGE_SMEM);
    cudaFuncSetAttribute(k_node_mma, cudaFuncAttributeMaxDynamicSharedMemorySize, NODE_SMEM);

    k_zero<<<2048, 256>>>(feats, W_edge, W_node);
    k_hist<<<640, 256>>>(dst, etypes, ntypes);
    k_scatter<<<320, 256>>>(src, dst, etypes, ntypes);
    k_edge_v12<<<EDGE_GRID, 512, EDGE_SMEM>>>(b_edge);
    k_node_mma<<<NG, 256, NODE_SMEM>>>(b_node, ntypes, out);
}

// round 13
// speedup vs baseline: 2.3252x; 1.5188x over previous
#include <cuda_runtime.h>
#include <cuda_fp16.h>
#include <cstdint>

#define N_NODES 50000
#define N_EDGES 640000
#define D 128
#define N_RELS 16
#define N_NT 8
#define TILE 128

#define EG (N_EDGES / TILE + 2 * N_RELS)  /* bins padded to 2-tile multiples: 5032 */
#define NG ((N_NODES + TILE - 1) / TILE + N_NT)
#define E_PAD (EG * TILE)
#define N_PAD (NG * TILE)

#define SROWH 144                          /* half stride: 288B == 32 mod 128 -> conflict-free LDS.64 */
#define EDGE_SMEM (384 * SROWH * 2)        /* sB(128) + sA(256) rows = 110592 B */
#define NODE_SMEM (256 * SROWH * 2)        /* 73728 B */
#define EDGE_GRID (EG / 2)

/* ------------------------------ scratch ------------------------------ */
__device__ int    g_counts[N_NODES * N_RELS];
__device__ int    g_rel_cnt[N_RELS];
__device__ int    g_rel_cur[N_RELS];
__device__ int    g_nt_cnt[N_NT];
__device__ int    g_nt_cur[N_NT];
__device__ int    g_esrc[E_PAD];
__device__ int    g_edst[E_PAD];
__device__ float  g_einv[E_PAD];
__device__ int    g_erel[E_PAD];
__device__ int    g_nperm[N_PAD];
__device__ float  g_agg[N_NODES * D];
__device__ int    g_ntiles[2];
__device__ __half g_WTh[N_RELS * D * D];   /* W_edge^T, fp16, psi(k)-interleaved, pi(f)-row-permuted */
__device__ __half g_WnTh[N_NT * D * D];    /* W_node^T, fp16, psi(k)-interleaved */
__device__ __half g_featsH[N_NODES * D];   /* feats, fp16, psi(k)-interleaved */
__device__ int    g_hist_done;

/* ------------------------------ helpers ------------------------------ */
__device__ __forceinline__ uint32_t smem_u32(const void* p) {
    uint32_t a;
    asm("{ .reg .u64 t; cvta.to.shared.u64 t, %1; cvt.u32.u64 %0, t; }" : "=r"(a) : "l"(p));
    return a;
}
__device__ __forceinline__ void cpa16(uint32_t dstS, const void* src) {
    asm volatile("cp.async.cg.shared.global [%0], [%1], 16;" :: "r"(dstS), "l"(src));
}
__device__ __forceinline__ void mma16(float* c, const uint32_t* a, const uint32_t* b) {
    asm volatile(
        "mma.sync.aligned.m16n8k16.row.col.f32.f16.f16.f32 "
        "{%0,%1,%2,%3}, {%4,%5,%6,%7}, {%8,%9}, {%0,%1,%2,%3};"
        : "+f"(c[0]), "+f"(c[1]), "+f"(c[2]), "+f"(c[3])
        : "r"(a[0]), "r"(a[1]), "r"(a[2]), "r"(a[3]), "r"(b[0]), "r"(b[1]));
}
__device__ __forceinline__ void red4(float* p, float x, float y, float z, float w) {
    asm volatile("red.global.add.v4.f32 [%0], {%1,%2,%3,%4};"
                 :: "l"(p), "f"(x), "f"(y), "f"(z), "f"(w) : "memory");
}
/* psi: within 16-col block, order becomes [2lr, 2lr+1, 2lr+8, 2lr+9] contiguous */
__device__ __forceinline__ int psik(int k) {
    return (k & ~15) | ((k & 6) << 1) | (((k >> 3) & 1) << 1) | (k & 1);
}
/* row permutation for v4 epilogue: within 16-row group, f=4a+2b+c -> p=8b+2a+c */
__device__ __forceinline__ int pif(int f) {
    int a = (f >> 2) & 3, b = (f >> 1) & 1, c = f & 1;
    return (f & ~15) | (b << 3) | (a << 1) | c;
}

/* ------------------------------ setup: zero + fp16 convert + transpose ------------------------------ */
__global__ void k_zero(const float* __restrict__ feats, const float* __restrict__ We,
                       const float* __restrict__ Wn) {
    int i = blockIdx.x * blockDim.x + threadIdx.x;
    int stride = gridDim.x * blockDim.x;
    for (int j = i; j < N_NODES * D; j += stride) {
        g_agg[j] = 0.0f;
        int n = j >> 7, d = j & 127;
        g_featsH[(n << 7) + psik(d)] = __float2half_rn(feats[j]);
    }
    for (int j = i; j < N_NODES * N_RELS; j += stride) g_counts[j] = 0;
    for (int j = i; j < E_PAD; j += stride) {
        g_edst[j] = -1;
        g_esrc[j] = 0;
        g_einv[j] = 0.0f;
        g_erel[j] = 0;
    }
    for (int j = i; j < N_PAD; j += stride) g_nperm[j] = -1;
    if (i < N_RELS) g_rel_cnt[i] = 0;
    if (i < N_NT) g_nt_cnt[i] = 0;
    if (i == 0) g_hist_done = 0;
    for (int j = i; j < N_RELS * D * D; j += stride) {
        int m = j >> 14, lin = j & 16383;
        int f = lin >> 7, d = lin & 127;
        g_WTh[(size_t)m * D * D + pif(f) * D + psik(d)] =
            __float2half_rn(We[(size_t)m * D * D + d * D + f]);
    }
    for (int j = i; j < N_NT * D * D; j += stride) {
        int m = j >> 14, lin = j & 16383;
        int f = lin >> 7, d = lin & 127;
        g_WnTh[(size_t)m * D * D + f * D + psik(d)] =
            __float2half_rn(Wn[(size_t)m * D * D + d * D + f]);
    }
}

/* ------------------------------ setup: histogram + last-block scan ------------------------------ */
__global__ void k_hist(const int* __restrict__ dst, const int* __restrict__ etypes,
                       const int* __restrict__ ntypes) {
    __shared__ int sh[N_RELS + N_NT];
    __shared__ int sLast;
    int tid = threadIdx.x;
    if (tid < N_RELS + N_NT) sh[tid] = 0;
    __syncthreads();
    int i = blockIdx.x * blockDim.x + tid;
    int stride = gridDim.x * blockDim.x;
    for (int e = i; e < N_EDGES; e += stride) {
        int t = etypes[e];
        atomicAdd(&sh[t], 1);
        atomicAdd(&g_counts[dst[e] * N_RELS + t], 1);
    }
    for (int n = i; n < N_NODES; n += stride) atomicAdd(&sh[N_RELS + ntypes[n]], 1);
    __syncthreads();
    if (tid < N_RELS) atomicAdd(&g_rel_cnt[tid], sh[tid]);
    else if (tid < N_RELS + N_NT) atomicAdd(&g_nt_cnt[tid - N_RELS], sh[tid]);

    __threadfence();
    __syncthreads();
    if (tid == 0) sLast = (atomicAdd(&g_hist_done, 1) == (int)gridDim.x - 1) ? 1 : 0;
    __syncthreads();
    if (sLast && tid == 0) {
        int off = 0;
        for (int t = 0; t < N_RELS; t++) {
            g_rel_cur[t] = off;
            off += ((g_rel_cnt[t] + 2 * TILE - 1) / (2 * TILE)) * (2 * TILE); /* 256-aligned */
        }
        g_ntiles[0] = off / TILE;
        off = 0;
        for (int t = 0; t < N_NT; t++) {
            g_nt_cur[t] = off;
            off += ((g_nt_cnt[t] + TILE - 1) / TILE) * TILE;
        }
        g_ntiles[1] = off / TILE;
    }
}

/* ------------------------------ setup: stable chunked scatter + per-edge meta ------------------------------ */
__global__ void k_scatter(const int* __restrict__ src, const int* __restrict__ dst,
                          const int* __restrict__ etypes, const int* __restrict__ ntypes) {
    __shared__ int s_cnt[N_RELS], s_base[N_RELS];
    const int CH = 2048;
    int tid = threadIdx.x;

    int nch = (N_EDGES + CH - 1) / CH;
    for (int ch = blockIdx.x; ch < nch; ch += gridDim.x) {
        int lo = ch * CH, hi = min(lo + CH, N_EDGES);
        if (tid < N_RELS) s_cnt[tid] = 0;
        __syncthreads();
        for (int e = lo + tid; e < hi; e += blockDim.x) atomicAdd(&s_cnt[etypes[e]], 1);
        __syncthreads();
        if (tid < N_RELS) {
            s_base[tid] = atomicAdd(&g_rel_cur[tid], s_cnt[tid]);
            s_cnt[tid] = 0;
        }
        __syncthreads();
        for (int e = lo + tid; e < hi; e += blockDim.x) {
            int t = etypes[e];
            int pos = s_base[t] + atomicAdd(&s_cnt[t], 1);
            int dn = dst[e];
            g_esrc[pos] = src[e];
            g_edst[pos] = dn;
            g_erel[pos] = t;
            g_einv[pos] = 1.0f / (float)g_counts[dn * N_RELS + t];
        }
        __syncthreads();
    }
    nch = (N_NODES + CH - 1) / CH;
    for (int ch = blockIdx.x; ch < nch; ch += gridDim.x) {
        int lo = ch * CH, hi = min(lo + CH, N_NODES);
        if (tid < N_NT) s_cnt[tid] = 0;
        __syncthreads();
        for (int n = lo + tid; n < hi; n += blockDim.x) atomicAdd(&s_cnt[ntypes[n]], 1);
        __syncthreads();
        if (tid < N_NT) {
            s_base[tid] = atomicAdd(&g_nt_cur[tid], s_cnt[tid]);
            s_cnt[tid] = 0;
        }
        __syncthreads();
        for (int n = lo + tid; n < hi; n += blockDim.x) {
            int t = ntypes[n];
            g_nperm[s_base[t] + atomicAdd(&s_cnt[t], 1)] = n;
        }
        __syncthreads();
    }
}

/* ------------------------------ edge GEMM: fused 256x128 fp16 pair per CTA, 512 thr ------------------------------ */
__global__ __launch_bounds__(512, 1) void k_edge_v13(const float* __restrict__ b_edge) {
    const int t0 = 2 * blockIdx.x;
    if (t0 >= g_ntiles[0]) return;

    extern __shared__ __half smh[];
    __half* sB = smh;                     /* [128][SROWH] */
    __half* sA = smh + 128 * SROWH;       /* [256][SROWH] */

    __shared__ int sDst[2 * TILE];
    __shared__ float sInv[2 * TILE];
    __shared__ float sBias[TILE];

    const int tid = threadIdx.x;
    const int base = t0 * TILE;
    const int r = tid >> 2, q = tid & 3;

    const int rel = g_erel[base];

    /* B via cp.async: 128 rows x 256B = 2048 x 16B chunks */
    {
        const __half* Wr = g_WTh + (size_t)rel * D * D;
#pragma unroll
        for (int i = 0; i < 4; i++) {
            int lin = tid + 512 * i;
            int f = lin >> 4, c = lin & 15;
            cpa16(smem_u32(sB + f * SROWH + c * 8), Wr + f * D + c * 8);
        }
    }
    /* A0+A1 via cp.async: raw 256B row copies (featsH psi-interleaved); 4 thr/row */
#pragma unroll
    for (int t = 0; t < 2; t++) {
        int s = g_esrc[base + t * TILE + r];
        const __half* fp = g_featsH + ((size_t)s << 7) + q * 32;
        uint32_t ap = smem_u32(sA + (t * 128 + r) * SROWH + q * 32);
#pragma unroll
        for (int c = 0; c < 4; c++) cpa16(ap + c * 16, fp + c * 8);
    }
    asm volatile("cp.async.commit_group;" ::: "memory");

    /* meta + bias */
    if (q < 2) {
        sDst[q * TILE + r] = g_edst[base + q * TILE + r];
        sInv[q * TILE + r] = g_einv[base + q * TILE + r];
    }
    if (tid < TILE) sBias[tid] = b_edge[rel * D + tid];

    asm volatile("cp.async.wait_group 0;" ::: "memory");
    __syncthreads();   /* the ONLY barrier */

    const int wid = tid >> 5, lane = tid & 31;
    const int wm = wid & 3, wn = wid >> 2;
    const int c_base = wn * 32;
    const int lq = lane >> 2, lr = lane & 3;
    const __half* sAw = sA + wm * 64 * SROWH;   /* warp's 64-row slab of the fused 256 rows */

    float acc[4][4][4];
#pragma unroll
    for (int mt = 0; mt < 4; mt++)
#pragma unroll
        for (int nt = 0; nt < 4; nt++)
#pragma unroll
            for (int j = 0; j < 4; j++) acc[mt][nt][j] = 0.0f;

#pragma unroll
    for (int k0 = 0; k0 < 8; k0++) {
        const int koff = k0 * 16 + lr * 4;   /* half units */
        uint32_t a[4][4], bb[4][2];
#pragma unroll
        for (int mt = 0; mt < 4; mt++) {
            int row = mt * 16 + lq;
            uint2 p0 = *(const uint2*)(sAw + row * SROWH + koff);
            uint2 p1 = *(const uint2*)(sAw + (row + 8) * SROWH + koff);
            a[mt][0] = p0.x;  /* (row,   2lr..2lr+1) */
            a[mt][1] = p1.x;  /* (row+8, 2lr..2lr+1) */
            a[mt][2] = p0.y;  /* (row,   2lr+8..9)   */
            a[mt][3] = p1.y;  /* (row+8, 2lr+8..9)   */
        }
#pragma unroll
        for (int nt = 0; nt < 4; nt++) {
            int n = c_base + nt * 8 + lq;
            uint2 pb = *(const uint2*)(sB + n * SROWH + koff);
            bb[nt][0] = pb.x;
            bb[nt][1] = pb.y;
        }
#pragma unroll
        for (int mt = 0; mt < 4; mt++)
#pragma unroll
            for (int nt = 0; nt < 4; nt++) mma16(acc[mt][nt], a[mt], bb[nt]);
    }

    /* epilogue: fused row = wm*64 + mt*16 + lq + h*8; thread owns logical cols c_base+16j+4lr.. */
#pragma unroll
    for (int mt = 0; mt < 4; mt++)
#pragma unroll
        for (int h = 0; h < 2; h++) {
            int rr = wm * 64 + mt * 16 + lq + h * 8;
            int dn = sDst[rr];
            if (dn < 0) continue;
            float inv = sInv[rr];
            float* gb = g_agg + (size_t)dn * D;
#pragma unroll
            for (int j = 0; j < 2; j++) {
                int Lc = c_base + j * 16 + 4 * lr;
                float4 bv = *(const float4*)(sBias + Lc);
                float x = (acc[mt][2 * j][h * 2 + 0] + bv.x) * inv;
                float y = (acc[mt][2 * j][h * 2 + 1] + bv.y) * inv;
                float z = (acc[mt][2 * j + 1][h * 2 + 0] + bv.z) * inv;
                float w = (acc[mt][2 * j + 1][h * 2 + 1] + bv.w) * inv;
                red4(gb + Lc, x, y, z, w);
            }
        }
}

/* ------------------------------ node GEMM fp16 + residual + relu ------------------------------ */
__global__ __launch_bounds__(256, 1) void k_node_v13(
    const float* __restrict__ b_node, const int* __restrict__ ntypes,
    float* __restrict__ out) {
    if ((int)blockIdx.x >= g_ntiles[1]) return;

    extern __shared__ __half smh[];
    __half* sA = smh;                     /* [128][SROWH] */
    __half* sB = smh + 128 * SROWH;       /* [128][SROWH] */

    __shared__ int sNode[TILE];
    __shared__ float sBias[TILE];
    __shared__ int sNt;

    const int tid = threadIdx.x, wid = tid >> 5, lane = tid & 31;
    const int base = blockIdx.x * TILE;

    if (tid < TILE) {
        int n = g_nperm[base + tid];
        sNode[tid] = n;
        if (tid == 0) sNt = ntypes[n];
    }
    __syncthreads();
    const int nt_ = sNt;
    if (tid < TILE) sBias[tid] = b_node[nt_ * D + tid];

    {
        int r = tid >> 1, h = tid & 1;
        int n = sNode[r];
        const uint4* fp = (const uint4*)(g_featsH + ((size_t)(n >= 0 ? n : 0) << 7)) + h * 8;
        __half* ap = sA + r * SROWH + h * 64;
#pragma unroll
        for (int i = 0; i < 8; i++) *(uint4*)(ap + i * 8) = fp[i];
    }
    {
        const __half* Wr = g_WnTh + (size_t)nt_ * D * D;
#pragma unroll
        for (int i = 0; i < 8; i++) {
            int lin = tid + 256 * i;
            int f = lin >> 4, c = lin & 15;
            *(uint4*)(sB + f * SROWH + c * 8) = *(const uint4*)(Wr + f * D + c * 8);
        }
    }
    __syncthreads();

    const int wm = wid & 1, wn = wid >> 1;
    const int r_base = wm * 64, c_base = wn * 32;
    const int lq = lane >> 2, lr = lane & 3;

    float acc[4][4][4];
#pragma unroll
    for (int mt = 0; mt < 4; mt++)
#pragma unroll
        for (int ntl = 0; ntl < 4; ntl++)
#pragma unroll
            for (int j = 0; j < 4; j++) acc[mt][ntl][j] = 0.0f;

#pragma unroll
    for (int k0 = 0; k0 < 8; k0++) {
        const int koff = k0 * 16 + lr * 4;
        uint32_t a[4][4], b[4][2];
#pragma unroll
        for (int mt = 0; mt < 4; mt++) {
            int row = r_base + mt * 16 + lq;
            uint2 p0 = *(const uint2*)(sA + row * SROWH + koff);
            uint2 p1 = *(const uint2*)(sA + (row + 8) * SROWH + koff);
            a[mt][0] = p0.x;
            a[mt][1] = p1.x;
            a[mt][2] = p0.y;
            a[mt][3] = p1.y;
        }
#pragma unroll
        for (int ntl = 0; ntl < 4; ntl++) {
            int n = c_base + ntl * 8 + lq;
            uint2 pb = *(const uint2*)(sB + n * SROWH + koff);
            b[ntl][0] = pb.x;
            b[ntl][1] = pb.y;
        }
#pragma unroll
        for (int mt = 0; mt < 4; mt++)
#pragma unroll
            for (int ntl = 0; ntl < 4; ntl++) mma16(acc[mt][ntl], a[mt], b[ntl]);
    }

    /* epilogue: relu(acc + bias + agg) -> out (cols 2lr,2lr+1 per n-tile; plain stores) */
#pragma unroll
    for (int mt = 0; mt < 4; mt++) {
        int row0 = r_base + mt * 16 + lq;
#pragma unroll
        for (int h = 0; h < 2; h++) {
            int rr = row0 + h * 8;
            int n = sNode[rr];
            if (n < 0) continue;
            const float* ab = g_agg + (size_t)n * D;
            float* ob = out + (size_t)n * D;
#pragma unroll
            for (int ntl = 0; ntl < 4; ntl++) {
                int col = c_base + ntl * 8 + lr * 2;
                float2 ag = *(const float2*)(ab + col);
                float2 o;
                o.x = fmaxf(acc[mt][ntl][h * 2 + 0] + sBias[col] + ag.x, 0.0f);
                o.y = fmaxf(acc[mt][ntl][h * 2 + 1] + sBias[col + 1] + ag.y, 0.0f);
                *(float2*)(ob + col) = o;
            }
        }
    }
}

/* ------------------------------ launch ------------------------------ */
extern "C" void kernel_launch(void* const* d_in, const int* in_sizes, int n_in,
                              void* d_out, int out_size) {
    const float* feats  = (const float*)d_in[0];
    const float* W_edge = (const float*)d_in[1];
    const float* b_edge = (const float*)d_in[2];
    const float* W_node = (const float*)d_in[3];
    const float* b_node = (const float*)d_in[4];
    const int* src    = (const int*)d_in[5];
    const int* dst    = (const int*)d_in[6];
    const int* ntypes = (const int*)d_in[7];
    const int* etypes = (const int*)d_in[8];
    float* out = (float*)d_out;
    (void)in_sizes; (void)n_in; (void)out_size;

    cudaFuncSetAttribute(k_edge_v13, cudaFuncAttributeMaxDynamicSharedMemorySize, EDGE_SMEM);
    cudaFuncSetAttribute(k_node_v13, cudaFuncAttributeMaxDynamicSharedMemorySize, NODE_SMEM);

    k_zero<<<2048, 256>>>(feats, W_edge, W_node);
    k_hist<<<640, 256>>>(dst, etypes, ntypes);
    k_scatter<<<320, 256>>>(src, dst, etypes, ntypes);
    k_edge_v13<<<EDGE_GRID, 512, EDGE_SMEM>>>(b_edge);
    k_node_v13<<<NG, 256, NODE_SMEM>>>(b_node, ntypes, out);
}

// round 14
// speedup vs baseline: 2.3730x; 1.0206x over previous
#include <cuda_runtime.h>
#include <cuda_fp16.h>
#include <cstdint>

#define N_NODES 50000
#define N_EDGES 640000
#define D 128
#define N_RELS 16
#define N_NT 8
#define TILE 128

#define EG (N_EDGES / TILE + 4 * N_RELS)  /* bins padded to 4-tile multiples: 5064 */
#define NG ((N_NODES + TILE - 1) / TILE + N_NT)
#define E_PAD (EG * TILE)
#define N_PAD (NG * TILE)

#define SROWH 144                          /* half stride: 288B == 32 mod 128 -> conflict-free LDS.64 */
#define EDGE_SMEM ((128 + 512) * SROWH * 2) /* sB(128) + sA(512) rows = 184320 B */
#define NODE_SMEM (256 * SROWH * 2)        /* 73728 B */
#define EDGE_GRID (EG / 4)                 /* 1266 */

/* ------------------------------ scratch ------------------------------ */
__device__ int    g_counts[N_NODES * N_RELS];
__device__ int    g_rel_cnt[N_RELS];
__device__ int    g_rel_cur[N_RELS];
__device__ int    g_nt_cnt[N_NT];
__device__ int    g_nt_cur[N_NT];
__device__ int    g_esrc[E_PAD];
__device__ int    g_edst[E_PAD];
__device__ float  g_einv[E_PAD];
__device__ int    g_erel[E_PAD];
__device__ int    g_nperm[N_PAD];
__device__ float  g_agg[N_NODES * D];
__device__ int    g_ntiles[2];
__device__ __half g_WTh[N_RELS * D * D];   /* W_edge^T, fp16, psi(k)-interleaved, pi(f)-row-permuted */
__device__ __half g_WnTh[N_NT * D * D];    /* W_node^T, fp16, psi(k)-interleaved */
__device__ __half g_featsH[N_NODES * D];   /* feats, fp16, psi(k)-interleaved */
__device__ int    g_hist_done;

/* ------------------------------ helpers ------------------------------ */
__device__ __forceinline__ uint32_t smem_u32(const void* p) {
    uint32_t a;
    asm("{ .reg .u64 t; cvta.to.shared.u64 t, %1; cvt.u32.u64 %0, t; }" : "=r"(a) : "l"(p));
    return a;
}
__device__ __forceinline__ void cpa16(uint32_t dstS, const void* src) {
    asm volatile("cp.async.cg.shared.global [%0], [%1], 16;" :: "r"(dstS), "l"(src));
}
__device__ __forceinline__ void mma16(float* c, const uint32_t* a, const uint32_t* b) {
    asm volatile(
        "mma.sync.aligned.m16n8k16.row.col.f32.f16.f16.f32 "
        "{%0,%1,%2,%3}, {%4,%5,%6,%7}, {%8,%9}, {%0,%1,%2,%3};"
        : "+f"(c[0]), "+f"(c[1]), "+f"(c[2]), "+f"(c[3])
        : "r"(a[0]), "r"(a[1]), "r"(a[2]), "r"(a[3]), "r"(b[0]), "r"(b[1]));
}
__device__ __forceinline__ void red4(float* p, float x, float y, float z, float w) {
    asm volatile("red.global.add.v4.f32 [%0], {%1,%2,%3,%4};"
                 :: "l"(p), "f"(x), "f"(y), "f"(z), "f"(w) : "memory");
}
/* psi: within 16-col block, order becomes [2lr, 2lr+1, 2lr+8, 2lr+9] contiguous */
__device__ __forceinline__ int psik(int k) {
    return (k & ~15) | ((k & 6) << 1) | (((k >> 3) & 1) << 1) | (k & 1);
}
/* row permutation for v4 epilogue: within 16-row group, f=4a+2b+c -> p=8b+2a+c */
__device__ __forceinline__ int pif(int f) {
    int a = (f >> 2) & 3, b = (f >> 1) & 1, c = f & 1;
    return (f & ~15) | (b << 3) | (a << 1) | c;
}

/* ------------------------------ setup: zero + fp16 convert + transpose ------------------------------ */
__global__ void k_zero(const float* __restrict__ feats, const float* __restrict__ We,
                       const float* __restrict__ Wn) {
    int i = blockIdx.x * blockDim.x + threadIdx.x;
    int stride = gridDim.x * blockDim.x;
    for (int j = i; j < N_NODES * D; j += stride) {
        g_agg[j] = 0.0f;
        int n = j >> 7, d = j & 127;
        g_featsH[(n << 7) + psik(d)] = __float2half_rn(feats[j]);
    }
    for (int j = i; j < N_NODES * N_RELS; j += stride) g_counts[j] = 0;
    for (int j = i; j < E_PAD; j += stride) {
        g_edst[j] = -1;
        g_esrc[j] = 0;
        g_erel[j] = 0;
    }
    for (int j = i; j < N_PAD; j += stride) g_nperm[j] = -1;
    if (i < N_RELS) g_rel_cnt[i] = 0;
    if (i < N_NT) g_nt_cnt[i] = 0;
    if (i == 0) g_hist_done = 0;
    for (int j = i; j < N_RELS * D * D; j += stride) {
        int m = j >> 14, lin = j & 16383;
        int f = lin >> 7, d = lin & 127;
        g_WTh[(size_t)m * D * D + pif(f) * D + psik(d)] =
            __float2half_rn(We[(size_t)m * D * D + d * D + f]);
    }
    for (int j = i; j < N_NT * D * D; j += stride) {
        int m = j >> 14, lin = j & 16383;
        int f = lin >> 7, d = lin & 127;
        g_WnTh[(size_t)m * D * D + f * D + psik(d)] =
            __float2half_rn(Wn[(size_t)m * D * D + d * D + f]);
    }
}

/* ------------------------------ setup: histogram + last-block scan ------------------------------ */
__global__ void k_hist(const int* __restrict__ dst, const int* __restrict__ etypes,
                       const int* __restrict__ ntypes) {
    __shared__ int sh[N_RELS + N_NT];
    __shared__ int sLast;
    int tid = threadIdx.x;
    if (tid < N_RELS + N_NT) sh[tid] = 0;
    __syncthreads();
    int i = blockIdx.x * blockDim.x + tid;
    int stride = gridDim.x * blockDim.x;
    for (int e = i; e < N_EDGES; e += stride) {
        int t = etypes[e];
        atomicAdd(&sh[t], 1);
        atomicAdd(&g_counts[dst[e] * N_RELS + t], 1);
    }
    for (int n = i; n < N_NODES; n += stride) atomicAdd(&sh[N_RELS + ntypes[n]], 1);
    __syncthreads();
    if (tid < N_RELS) atomicAdd(&g_rel_cnt[tid], sh[tid]);
    else if (tid < N_RELS + N_NT) atomicAdd(&g_nt_cnt[tid - N_RELS], sh[tid]);

    __threadfence();
    __syncthreads();
    if (tid == 0) sLast = (atomicAdd(&g_hist_done, 1) == (int)gridDim.x - 1) ? 1 : 0;
    __syncthreads();
    if (sLast && tid == 0) {
        int off = 0;
        for (int t = 0; t < N_RELS; t++) {
            g_rel_cur[t] = off;
            off += ((g_rel_cnt[t] + 4 * TILE - 1) / (4 * TILE)) * (4 * TILE); /* 512-aligned */
        }
        g_ntiles[0] = off / TILE;   /* multiple of 4 */
        off = 0;
        for (int t = 0; t < N_NT; t++) {
            g_nt_cur[t] = off;
            off += ((g_nt_cnt[t] + TILE - 1) / TILE) * TILE;
        }
        g_ntiles[1] = off / TILE;
    }
}

/* ------------------------------ setup: stable chunked scatter + per-edge meta ------------------------------ */
__global__ void k_scatter(const int* __restrict__ src, const int* __restrict__ dst,
                          const int* __restrict__ etypes, const int* __restrict__ ntypes) {
    __shared__ int s_cnt[N_RELS], s_base[N_RELS];
    const int CH = 2048;
    int tid = threadIdx.x;

    int nch = (N_EDGES + CH - 1) / CH;
    for (int ch = blockIdx.x; ch < nch; ch += gridDim.x) {
        int lo = ch * CH, hi = min(lo + CH, N_EDGES);
        if (tid < N_RELS) s_cnt[tid] = 0;
        __syncthreads();
        for (int e = lo + tid; e < hi; e += blockDim.x) atomicAdd(&s_cnt[etypes[e]], 1);
        __syncthreads();
        if (tid < N_RELS) {
            s_base[tid] = atomicAdd(&g_rel_cur[tid], s_cnt[tid]);
            s_cnt[tid] = 0;
        }
        __syncthreads();
        for (int e = lo + tid; e < hi; e += blockDim.x) {
            int t = etypes[e];
            int pos = s_base[t] + atomicAdd(&s_cnt[t], 1);
            int dn = dst[e];
            g_esrc[pos] = src[e];
            g_edst[pos] = dn;
            g_erel[pos] = t;
            g_einv[pos] = 1.0f / (float)g_counts[dn * N_RELS + t];
        }
        __syncthreads();
    }
    nch = (N_NODES + CH - 1) / CH;
    for (int ch = blockIdx.x; ch < nch; ch += gridDim.x) {
        int lo = ch * CH, hi = min(lo + CH, N_NODES);
        if (tid < N_NT) s_cnt[tid] = 0;
        __syncthreads();
        for (int n = lo + tid; n < hi; n += blockDim.x) atomicAdd(&s_cnt[ntypes[n]], 1);
        __syncthreads();
        if (tid < N_NT) {
            s_base[tid] = atomicAdd(&g_nt_cur[tid], s_cnt[tid]);
            s_cnt[tid] = 0;
        }
        __syncthreads();
        for (int n = lo + tid; n < hi; n += blockDim.x) {
            int t = ntypes[n];
            g_nperm[s_base[t] + atomicAdd(&s_cnt[t], 1)] = n;
        }
        __syncthreads();
    }
}

/* ------------------------------ edge GEMM: 512-row quad per CTA, two-phase mainloop ------------------------------ */
/* Bins 512-aligned => all 4 tiles share rel. Fill: group0 = B+A0+A1, group1 = A2+A3.
 * Half 0 (rows 0-255) computes while A2/A3 stream; half 0's red.v4 drain during
 * half 1's mainloop. B amortized over 512 rows. */
__global__ __launch_bounds__(512, 1) void k_edge_v14(const float* __restrict__ b_edge) {
    const int t0 = 4 * blockIdx.x;
    if (t0 >= g_ntiles[0]) return;

    extern __shared__ __half smh[];
    __half* sB = smh;                     /* [128][SROWH] */
    __half* sA = smh + 128 * SROWH;       /* [512][SROWH] */

    __shared__ int sDst[4 * TILE];
    __shared__ float sInv[4 * TILE];
    __shared__ float sBias[TILE];

    const int tid = threadIdx.x;
    const int base = t0 * TILE;
    const int r = tid >> 2, q = tid & 3;

    const int rel = g_erel[base];

    /* group 0: B + A0 + A1 */
    {
        const __half* Wr = g_WTh + (size_t)rel * D * D;
#pragma unroll
        for (int i = 0; i < 4; i++) {
            int lin = tid + 512 * i;
            int f = lin >> 4, c = lin & 15;
            cpa16(smem_u32(sB + f * SROWH + c * 8), Wr + f * D + c * 8);
        }
    }
#pragma unroll
    for (int t = 0; t < 2; t++) {
        int s = g_esrc[base + t * TILE + r];
        const __half* fp = g_featsH + ((size_t)s << 7) + q * 32;
        uint32_t ap = smem_u32(sA + (t * 128 + r) * SROWH + q * 32);
#pragma unroll
        for (int c = 0; c < 4; c++) cpa16(ap + c * 16, fp + c * 8);
    }
    asm volatile("cp.async.commit_group;" ::: "memory");
    /* group 1: A2 + A3 */
#pragma unroll
    for (int t = 2; t < 4; t++) {
        int s = g_esrc[base + t * TILE + r];
        const __half* fp = g_featsH + ((size_t)s << 7) + q * 32;
        uint32_t ap = smem_u32(sA + (t * 128 + r) * SROWH + q * 32);
#pragma unroll
        for (int c = 0; c < 4; c++) cpa16(ap + c * 16, fp + c * 8);
    }
    asm volatile("cp.async.commit_group;" ::: "memory");

    /* meta + bias */
    sDst[tid] = g_edst[base + tid];
    sInv[tid] = g_einv[base + tid];
    if (tid < TILE) sBias[tid] = b_edge[rel * D + tid];

    asm volatile("cp.async.wait_group 1;" ::: "memory");
    __syncthreads();   /* B + A0 + A1 + meta visible */

    const int wid = tid >> 5, lane = tid & 31;
    const int wm = wid & 3, wn = wid >> 2;
    const int c_base = wn * 32;
    const int lq = lane >> 2, lr = lane & 3;

#pragma unroll
    for (int half = 0; half < 2; half++) {
        if (half == 1) {
            asm volatile("cp.async.wait_group 0;" ::: "memory");
            __syncthreads();   /* A2 + A3 visible everywhere */
        }
        const __half* sAw = sA + (half * 256 + wm * 64) * SROWH;

        float acc[4][4][4];
#pragma unroll
        for (int mt = 0; mt < 4; mt++)
#pragma unroll
            for (int nt = 0; nt < 4; nt++)
#pragma unroll
                for (int j = 0; j < 4; j++) acc[mt][nt][j] = 0.0f;

#pragma unroll
        for (int k0 = 0; k0 < 8; k0++) {
            const int koff = k0 * 16 + lr * 4;
            uint32_t a[4][4], bb[4][2];
#pragma unroll
            for (int mt = 0; mt < 4; mt++) {
                int row = mt * 16 + lq;
                uint2 p0 = *(const uint2*)(sAw + row * SROWH + koff);
                uint2 p1 = *(const uint2*)(sAw + (row + 8) * SROWH + koff);
                a[mt][0] = p0.x;
                a[mt][1] = p1.x;
                a[mt][2] = p0.y;
                a[mt][3] = p1.y;
            }
#pragma unroll
            for (int nt = 0; nt < 4; nt++) {
                int n = c_base + nt * 8 + lq;
                uint2 pb = *(const uint2*)(sB + n * SROWH + koff);
                bb[nt][0] = pb.x;
                bb[nt][1] = pb.y;
            }
#pragma unroll
            for (int mt = 0; mt < 4; mt++)
#pragma unroll
                for (int nt = 0; nt < 4; nt++) mma16(acc[mt][nt], a[mt], bb[nt]);
        }

        /* epilogue: fire-and-forget red.v4; drains during next half's mainloop */
#pragma unroll
        for (int mt = 0; mt < 4; mt++)
#pragma unroll
            for (int h = 0; h < 2; h++) {
                int rr = half * 256 + wm * 64 + mt * 16 + lq + h * 8;
                int dn = sDst[rr];
                if (dn < 0) continue;
                float inv = sInv[rr];
                float* gb = g_agg + (size_t)dn * D;
#pragma unroll
                for (int j = 0; j < 2; j++) {
                    int Lc = c_base + j * 16 + 4 * lr;
                    float4 bv = *(const float4*)(sBias + Lc);
                    float x = (acc[mt][2 * j][h * 2 + 0] + bv.x) * inv;
                    float y = (acc[mt][2 * j][h * 2 + 1] + bv.y) * inv;
                    float z = (acc[mt][2 * j + 1][h * 2 + 0] + bv.z) * inv;
                    float w = (acc[mt][2 * j + 1][h * 2 + 1] + bv.w) * inv;
                    red4(gb + Lc, x, y, z, w);
                }
            }
    }
}

/* ------------------------------ node GEMM fp16 + residual + relu ------------------------------ */
__global__ __launch_bounds__(256, 1) void k_node_v14(
    const float* __restrict__ b_node, const int* __restrict__ ntypes,
    float* __restrict__ out) {
    if ((int)blockIdx.x >= g_ntiles[1]) return;

    extern __shared__ __half smh[];
    __half* sA = smh;
    __half* sB = smh + 128 * SROWH;

    __shared__ int sNode[TILE];
    __shared__ float sBias[TILE];
    __shared__ int sNt;

    const int tid = threadIdx.x, wid = tid >> 5, lane = tid & 31;
    const int base = blockIdx.x * TILE;

    if (tid < TILE) {
        int n = g_nperm[base + tid];
        sNode[tid] = n;
        if (tid == 0) sNt = ntypes[n];
    }
    __syncthreads();
    const int nt_ = sNt;
    if (tid < TILE) sBias[tid] = b_node[nt_ * D + tid];

    {
        int r = tid >> 1, h = tid & 1;
        int n = sNode[r];
        const uint4* fp = (const uint4*)(g_featsH + ((size_t)(n >= 0 ? n : 0) << 7)) + h * 8;
        __half* ap = sA + r * SROWH + h * 64;
#pragma unroll
        for (int i = 0; i < 8; i++) *(uint4*)(ap + i * 8) = fp[i];
    }
    {
        const __half* Wr = g_WnTh + (size_t)nt_ * D * D;
#pragma unroll
        for (int i = 0; i < 8; i++) {
            int lin = tid + 256 * i;
            int f = lin >> 4, c = lin & 15;
            *(uint4*)(sB + f * SROWH + c * 8) = *(const uint4*)(Wr + f * D + c * 8);
        }
    }
    __syncthreads();

    const int wm = wid & 1, wn = wid >> 1;
    const int r_base = wm * 64, c_base = wn * 32;
    const int lq = lane >> 2, lr = lane & 3;

    float acc[4][4][4];
#pragma unroll
    for (int mt = 0; mt < 4; mt++)
#pragma unroll
        for (int ntl = 0; ntl < 4; ntl++)
#pragma unroll
            for (int j = 0; j < 4; j++) acc[mt][ntl][j] = 0.0f;

#pragma unroll
    for (int k0 = 0; k0 < 8; k0++) {
        const int koff = k0 * 16 + lr * 4;
        uint32_t a[4][4], b[4][2];
#pragma unroll
        for (int mt = 0; mt < 4; mt++) {
            int row = r_base + mt * 16 + lq;
            uint2 p0 = *(const uint2*)(sA + row * SROWH + koff);
            uint2 p1 = *(const uint2*)(sA + (row + 8) * SROWH + koff);
            a[mt][0] = p0.x;
            a[mt][1] = p1.x;
            a[mt][2] = p0.y;
            a[mt][3] = p1.y;
        }
#pragma unroll
        for (int ntl = 0; ntl < 4; ntl++) {
            int n = c_base + ntl * 8 + lq;
            uint2 pb = *(const uint2*)(sB + n * SROWH + koff);
            b[ntl][0] = pb.x;
            b[ntl][1] = pb.y;
        }
#pragma unroll
        for (int mt = 0; mt < 4; mt++)
#pragma unroll
            for (int ntl = 0; ntl < 4; ntl++) mma16(acc[mt][ntl], a[mt], b[ntl]);
    }

#pragma unroll
    for (int mt = 0; mt < 4; mt++) {
        int row0 = r_base + mt * 16 + lq;
#pragma unroll
        for (int h = 0; h < 2; h++) {
            int rr = row0 + h * 8;
            int n = sNode[rr];
            if (n < 0) continue;
            const float* ab = g_agg + (size_t)n * D;
            float* ob = out + (size_t)n * D;
#pragma unroll
            for (int ntl = 0; ntl < 4; ntl++) {
                int col = c_base + ntl * 8 + lr * 2;
                float2 ag = *(const float2*)(ab + col);
                float2 o;
                o.x = fmaxf(acc[mt][ntl][h * 2 + 0] + sBias[col] + ag.x, 0.0f);
                o.y = fmaxf(acc[mt][ntl][h * 2 + 1] + sBias[col + 1] + ag.y, 0.0f);
                *(float2*)(ob + col) = o;
            }
        }
    }
}

/* ------------------------------ launch ------------------------------ */
extern "C" void kernel_launch(void* const* d_in, const int* in_sizes, int n_in,
                              void* d_out, int out_size) {
    const float* feats  = (const float*)d_in[0];
    const float* W_edge = (const float*)d_in[1];
    const float* b_edge = (const float*)d_in[2];
    const float* W_node = (const float*)d_in[3];
    const float* b_node = (const float*)d_in[4];
    const int* src    = (const int*)d_in[5];
    const int* dst    = (const int*)d_in[6];
    const int* ntypes = (const int*)d_in[7];
    const int* etypes = (const int*)d_in[8];
    float* out = (float*)d_out;
    (void)in_sizes; (void)n_in; (void)out_size;

    cudaFuncSetAttribute(k_edge_v14, cudaFuncAttributeMaxDynamicSharedMemorySize, EDGE_SMEM);
    cudaFuncSetAttribute(k_node_v14, cudaFuncAttributeMaxDynamicSharedMemorySize, NODE_SMEM);

    k_zero<<<2048, 256>>>(feats, W_edge, W_node);
    k_hist<<<640, 256>>>(dst, etypes, ntypes);
    k_scatter<<<320, 256>>>(src, dst, etypes, ntypes);
    k_edge_v14<<<EDGE_GRID, 512, EDGE_SMEM>>>(b_edge);
    k_node_v14<<<NG, 256, NODE_SMEM>>>(b_node, ntypes, out);
}

// round 15
// speedup vs baseline: 2.3955x; 1.0095x over previous
#include <cuda_runtime.h>
#include <cuda_fp16.h>
#include <cstdint>

#define N_NODES 50000
#define N_EDGES 640000
#define D 128
#define N_RELS 16
#define N_NT 8
#define TILE 128

#define EG (N_EDGES / TILE + 4 * N_RELS)   /* edge bins padded to 4-tile multiples: 5064 */
#define NGP ((N_NODES + TILE - 1) / TILE + 2 * N_NT) /* node bins padded to 2-tile multiples: 407 */
#define E_PAD (EG * TILE)
#define N_PAD (NGP * TILE)

#define SROWH 144                           /* half stride: 288B == 32 mod 128 -> conflict-free LDS.64 */
#define EDGE_SMEM ((128 + 512) * SROWH * 2) /* 184320 B */
#define NODE_SMEM ((128 + 256) * SROWH * 2) /* 110592 B */
#define EDGE_GRID (EG / 4)                  /* 1266 */
#define NODE_GRID ((NGP + 1) / 2)           /* 204 */

/* ------------------------------ scratch ------------------------------ */
__device__ int    g_counts[N_NODES * N_RELS];
__device__ int    g_rel_cnt[N_RELS];
__device__ int    g_rel_start[N_RELS];
__device__ int    g_rel_cur[N_RELS];
__device__ int    g_nt_cnt[N_NT];
__device__ int    g_nt_start[N_NT];
__device__ int    g_nt_cur[N_NT];
__device__ int    g_esrc[E_PAD];
__device__ int    g_edst[E_PAD];
__device__ float  g_einv[E_PAD];
__device__ int    g_erel[E_PAD];
__device__ int    g_nperm[N_PAD];
__device__ int    g_ntt[N_PAD];
__device__ float  g_agg[N_NODES * D];
__device__ int    g_ntiles[2];
__device__ __align__(16) __half g_WTh[N_RELS * D * D];  /* W_edge^T, fp16, psi+pi */
__device__ __align__(16) __half g_WnTh[N_NT * D * D];   /* W_node^T, fp16, psi+pi */
__device__ __align__(16) __half g_featsH[N_NODES * D];  /* feats, fp16, psi */
__device__ int    g_hist_done;

/* ------------------------------ helpers ------------------------------ */
__device__ __forceinline__ uint32_t smem_u32(const void* p) {
    uint32_t a;
    asm("{ .reg .u64 t; cvta.to.shared.u64 t, %1; cvt.u32.u64 %0, t; }" : "=r"(a) : "l"(p));
    return a;
}
__device__ __forceinline__ void cpa16(uint32_t dstS, const void* src) {
    asm volatile("cp.async.cg.shared.global [%0], [%1], 16;" :: "r"(dstS), "l"(src));
}
__device__ __forceinline__ void mma16(float* c, const uint32_t* a, const uint32_t* b) {
    asm volatile(
        "mma.sync.aligned.m16n8k16.row.col.f32.f16.f16.f32 "
        "{%0,%1,%2,%3}, {%4,%5,%6,%7}, {%8,%9}, {%0,%1,%2,%3};"
        : "+f"(c[0]), "+f"(c[1]), "+f"(c[2]), "+f"(c[3])
        : "r"(a[0]), "r"(a[1]), "r"(a[2]), "r"(a[3]), "r"(b[0]), "r"(b[1]));
}
__device__ __forceinline__ void red4(float* p, float x, float y, float z, float w) {
    asm volatile("red.global.add.v4.f32 [%0], {%1,%2,%3,%4};"
                 :: "l"(p), "f"(x), "f"(y), "f"(z), "f"(w) : "memory");
}
/* psi: pairs (2t,2t+1) stay adjacent; fragment cols [2lr,2lr+1,2lr+8,2lr+9] contiguous */
__device__ __forceinline__ int psik(int k) {
    return (k & ~15) | ((k & 6) << 1) | (((k >> 3) & 1) << 1) | (k & 1);
}
/* row permutation for v4 epilogue: within 16-row group, f=4a+2b+c -> p=8b+2a+c */
__device__ __forceinline__ int pif(int f) {
    int a = (f >> 2) & 3, b = (f >> 1) & 1, c = f & 1;
    return (f & ~15) | (b << 3) | (a << 1) | c;
}

/* ------------------------------ setup: zero + fp16 convert + transpose ------------------------------ */
__global__ void k_zero(const float* __restrict__ feats, const float* __restrict__ We,
                       const float* __restrict__ Wn) {
    int i = blockIdx.x * blockDim.x + threadIdx.x;
    int stride = gridDim.x * blockDim.x;
    float4* agg4 = (float4*)g_agg;
    for (int j = i; j < N_NODES * D / 4; j += stride) agg4[j] = make_float4(0.f, 0.f, 0.f, 0.f);
    int4* cnt4 = (int4*)g_counts;
    for (int j = i; j < N_NODES * N_RELS / 4; j += stride) cnt4[j] = make_int4(0, 0, 0, 0);
    const float2* f2 = (const float2*)feats;
    for (int j = i; j < N_NODES * D / 2; j += stride) {
        int n = j >> 6, t = j & 63;
        float2 v = f2[j];
        *(__half2*)(g_featsH + (n << 7) + psik(2 * t)) = __floats2half2_rn(v.x, v.y);
    }
    if (i < N_RELS) g_rel_cnt[i] = 0;
    if (i < N_NT) g_nt_cnt[i] = 0;
    if (i == 0) g_hist_done = 0;
    for (int j = i; j < N_RELS * D * D; j += stride) {
        int m = j >> 14, lin = j & 16383;
        int f = lin >> 7, d = lin & 127;
        g_WTh[(size_t)m * D * D + pif(f) * D + psik(d)] =
            __float2half_rn(We[(size_t)m * D * D + d * D + f]);
    }
    for (int j = i; j < N_NT * D * D; j += stride) {
        int m = j >> 14, lin = j & 16383;
        int f = lin >> 7, d = lin & 127;
        g_WnTh[(size_t)m * D * D + pif(f) * D + psik(d)] =
            __float2half_rn(Wn[(size_t)m * D * D + d * D + f]);
    }
}

/* ------------------------------ setup: histogram + last-block scan ------------------------------ */
__global__ void k_hist(const int* __restrict__ dst, const int* __restrict__ etypes,
                       const int* __restrict__ ntypes) {
    __shared__ int sh[N_RELS + N_NT];
    __shared__ int sLast;
    int tid = threadIdx.x;
    if (tid < N_RELS + N_NT) sh[tid] = 0;
    __syncthreads();
    int i = blockIdx.x * blockDim.x + tid;
    int stride = gridDim.x * blockDim.x;
    for (int e = i; e < N_EDGES; e += stride) {
        int t = etypes[e];
        atomicAdd(&sh[t], 1);
        atomicAdd(&g_counts[dst[e] * N_RELS + t], 1);
    }
    for (int n = i; n < N_NODES; n += stride) atomicAdd(&sh[N_RELS + ntypes[n]], 1);
    __syncthreads();
    if (tid < N_RELS) atomicAdd(&g_rel_cnt[tid], sh[tid]);
    else if (tid < N_RELS + N_NT) atomicAdd(&g_nt_cnt[tid - N_RELS], sh[tid]);

    __threadfence();
    __syncthreads();
    if (tid == 0) sLast = (atomicAdd(&g_hist_done, 1) == (int)gridDim.x - 1) ? 1 : 0;
    __syncthreads();
    if (sLast && tid == 0) {
        int off = 0;
        for (int t = 0; t < N_RELS; t++) {
            g_rel_start[t] = off;
            g_rel_cur[t] = off;
            off += ((g_rel_cnt[t] + 4 * TILE - 1) / (4 * TILE)) * (4 * TILE); /* 512-aligned */
        }
        g_ntiles[0] = off / TILE;
        off = 0;
        for (int t = 0; t < N_NT; t++) {
            g_nt_start[t] = off;
            g_nt_cur[t] = off;
            off += ((g_nt_cnt[t] + 2 * TILE - 1) / (2 * TILE)) * (2 * TILE); /* 256-aligned */
        }
        g_ntiles[1] = off / TILE;
    }
}

/* ------------------------------ setup: pad bin tails + stable chunked scatter ------------------------------ */
__global__ void k_scatter(const int* __restrict__ src, const int* __restrict__ dst,
                          const int* __restrict__ etypes, const int* __restrict__ ntypes) {
    __shared__ int s_cnt[N_RELS], s_base[N_RELS];
    const int CH = 2048;
    int tid = threadIdx.x;

    /* pad bin tails (disjoint from scatter writes) */
    if (blockIdx.x < N_RELS) {
        int t = blockIdx.x;
        int lo = g_rel_start[t] + g_rel_cnt[t];
        int hi = g_rel_start[t] + ((g_rel_cnt[t] + 4 * TILE - 1) / (4 * TILE)) * (4 * TILE);
        for (int p = lo + tid; p < hi; p += blockDim.x) {
            g_edst[p] = -1;
            g_esrc[p] = 0;
        }
    } else if (blockIdx.x < N_RELS + N_NT) {
        int t = blockIdx.x - N_RELS;
        int lo = g_nt_start[t] + g_nt_cnt[t];
        int hi = g_nt_start[t] + ((g_nt_cnt[t] + 2 * TILE - 1) / (2 * TILE)) * (2 * TILE);
        for (int p = lo + tid; p < hi; p += blockDim.x) g_nperm[p] = -1;
    }

    int nch = (N_EDGES + CH - 1) / CH;
    for (int ch = blockIdx.x; ch < nch; ch += gridDim.x) {
        int lo = ch * CH, hi = min(lo + CH, N_EDGES);
        if (tid < N_RELS) s_cnt[tid] = 0;
        __syncthreads();
        for (int e = lo + tid; e < hi; e += blockDim.x) atomicAdd(&s_cnt[etypes[e]], 1);
        __syncthreads();
        if (tid < N_RELS) {
            s_base[tid] = atomicAdd(&g_rel_cur[tid], s_cnt[tid]);
            s_cnt[tid] = 0;
        }
        __syncthreads();
        for (int e = lo + tid; e < hi; e += blockDim.x) {
            int t = etypes[e];
            int pos = s_base[t] + atomicAdd(&s_cnt[t], 1);
            int dn = dst[e];
            g_esrc[pos] = src[e];
            g_edst[pos] = dn;
            g_erel[pos] = t;
            g_einv[pos] = 1.0f / (float)g_counts[dn * N_RELS + t];
        }
        __syncthreads();
    }
    nch = (N_NODES + CH - 1) / CH;
    for (int ch = blockIdx.x; ch < nch; ch += gridDim.x) {
        int lo = ch * CH, hi = min(lo + CH, N_NODES);
        if (tid < N_NT) s_cnt[tid] = 0;
        __syncthreads();
        for (int n = lo + tid; n < hi; n += blockDim.x) atomicAdd(&s_cnt[ntypes[n]], 1);
        __syncthreads();
        if (tid < N_NT) {
            s_base[tid] = atomicAdd(&g_nt_cur[tid], s_cnt[tid]);
            s_cnt[tid] = 0;
        }
        __syncthreads();
        for (int n = lo + tid; n < hi; n += blockDim.x) {
            int t = ntypes[n];
            int pos = s_base[t] + atomicAdd(&s_cnt[t], 1);
            g_nperm[pos] = n;
            g_ntt[pos] = t;
        }
        __syncthreads();
    }
}

/* ------------------------------ edge GEMM: 512-row quad per CTA (unchanged v14) ------------------------------ */
__global__ __launch_bounds__(512, 1) void k_edge_v15(const float* __restrict__ b_edge) {
    const int t0 = 4 * blockIdx.x;
    if (t0 >= g_ntiles[0]) return;

    extern __shared__ __half smh[];
    __half* sB = smh;
    __half* sA = smh + 128 * SROWH;

    __shared__ int sDst[4 * TILE];
    __shared__ float sInv[4 * TILE];
    __shared__ float sBias[TILE];

    const int tid = threadIdx.x;
    const int base = t0 * TILE;
    const int r = tid >> 2, q = tid & 3;

    const int rel = g_erel[base];

    {
        const __half* Wr = g_WTh + (size_t)rel * D * D;
#pragma unroll
        for (int i = 0; i < 4; i++) {
            int lin = tid + 512 * i;
            int f = lin >> 4, c = lin & 15;
            cpa16(smem_u32(sB + f * SROWH + c * 8), Wr + f * D + c * 8);
        }
    }
#pragma unroll
    for (int t = 0; t < 2; t++) {
        int s = g_esrc[base + t * TILE + r];
        const __half* fp = g_featsH + ((size_t)s << 7) + q * 32;
        uint32_t ap = smem_u32(sA + (t * 128 + r) * SROWH + q * 32);
#pragma unroll
        for (int c = 0; c < 4; c++) cpa16(ap + c * 16, fp + c * 8);
    }
    asm volatile("cp.async.commit_group;" ::: "memory");
#pragma unroll
    for (int t = 2; t < 4; t++) {
        int s = g_esrc[base + t * TILE + r];
        const __half* fp = g_featsH + ((size_t)s << 7) + q * 32;
        uint32_t ap = smem_u32(sA + (t * 128 + r) * SROWH + q * 32);
#pragma unroll
        for (int c = 0; c < 4; c++) cpa16(ap + c * 16, fp + c * 8);
    }
    asm volatile("cp.async.commit_group;" ::: "memory");

    sDst[tid] = g_edst[base + tid];
    sInv[tid] = g_einv[base + tid];
    if (tid < TILE) sBias[tid] = b_edge[rel * D + tid];

    asm volatile("cp.async.wait_group 1;" ::: "memory");
    __syncthreads();

    const int wid = tid >> 5, lane = tid & 31;
    const int wm = wid & 3, wn = wid >> 2;
    const int c_base = wn * 32;
    const int lq = lane >> 2, lr = lane & 3;

#pragma unroll
    for (int half = 0; half < 2; half++) {
        if (half == 1) {
            asm volatile("cp.async.wait_group 0;" ::: "memory");
            __syncthreads();
        }
        const __half* sAw = sA + (half * 256 + wm * 64) * SROWH;

        float acc[4][4][4];
#pragma unroll
        for (int mt = 0; mt < 4; mt++)
#pragma unroll
            for (int nt = 0; nt < 4; nt++)
#pragma unroll
                for (int j = 0; j < 4; j++) acc[mt][nt][j] = 0.0f;

#pragma unroll
        for (int k0 = 0; k0 < 8; k0++) {
            const int koff = k0 * 16 + lr * 4;
            uint32_t a[4][4], bb[4][2];
#pragma unroll
            for (int mt = 0; mt < 4; mt++) {
                int row = mt * 16 + lq;
                uint2 p0 = *(const uint2*)(sAw + row * SROWH + koff);
                uint2 p1 = *(const uint2*)(sAw + (row + 8) * SROWH + koff);
                a[mt][0] = p0.x;
                a[mt][1] = p1.x;
                a[mt][2] = p0.y;
                a[mt][3] = p1.y;
            }
#pragma unroll
            for (int nt = 0; nt < 4; nt++) {
                int n = c_base + nt * 8 + lq;
                uint2 pb = *(const uint2*)(sB + n * SROWH + koff);
                bb[nt][0] = pb.x;
                bb[nt][1] = pb.y;
            }
#pragma unroll
            for (int mt = 0; mt < 4; mt++)
#pragma unroll
                for (int nt = 0; nt < 4; nt++) mma16(acc[mt][nt], a[mt], bb[nt]);
        }

#pragma unroll
        for (int mt = 0; mt < 4; mt++)
#pragma unroll
            for (int h = 0; h < 2; h++) {
                int rr = half * 256 + wm * 64 + mt * 16 + lq + h * 8;
                int dn = sDst[rr];
                if (dn < 0) continue;
                float inv = sInv[rr];
                float* gb = g_agg + (size_t)dn * D;
#pragma unroll
                for (int j = 0; j < 2; j++) {
                    int Lc = c_base + j * 16 + 4 * lr;
                    float4 bv = *(const float4*)(sBias + Lc);
                    float x = (acc[mt][2 * j][h * 2 + 0] + bv.x) * inv;
                    float y = (acc[mt][2 * j][h * 2 + 1] + bv.y) * inv;
                    float z = (acc[mt][2 * j + 1][h * 2 + 0] + bv.z) * inv;
                    float w = (acc[mt][2 * j + 1][h * 2 + 1] + bv.w) * inv;
                    red4(gb + Lc, x, y, z, w);
                }
            }
    }
}

/* ------------------------------ node GEMM: fused 256-row pair, 512 thr, cp.async ------------------------------ */
__global__ __launch_bounds__(512, 1) void k_node_v15(
    const float* __restrict__ b_node, float* __restrict__ out) {
    const int t0 = 2 * blockIdx.x;
    if (t0 >= g_ntiles[1]) return;

    extern __shared__ __half smh[];
    __half* sB = smh;                     /* [128][SROWH], pi-permuted rows */
    __half* sA = smh + 128 * SROWH;       /* [256][SROWH] */

    __shared__ int sNode[2 * TILE];
    __shared__ float sBias[TILE];

    const int tid = threadIdx.x;
    const int base = t0 * TILE;

    const int nt_ = g_ntt[base];          /* ntype of this bin (base row always real) */

    /* B via cp.async */
    {
        const __half* Wr = g_WnTh + (size_t)nt_ * D * D;
#pragma unroll
        for (int i = 0; i < 4; i++) {
            int lin = tid + 512 * i;
            int f = lin >> 4, c = lin & 15;
            cpa16(smem_u32(sB + f * SROWH + c * 8), Wr + f * D + c * 8);
        }
    }
    /* A via cp.async: 2 threads per row, 128B each */
    {
        int r = tid >> 1, h = tid & 1;
        int n = g_nperm[base + r];
        const __half* fp = g_featsH + ((size_t)(n >= 0 ? n : 0) << 7) + h * 64;
        uint32_t ap = smem_u32(sA + r * SROWH + h * 64);
#pragma unroll
        for (int c = 0; c < 8; c++) cpa16(ap + c * 16, fp + c * 8);
    }
    asm volatile("cp.async.commit_group;" ::: "memory");

    /* meta + bias */
    if (tid < 2 * TILE) sNode[tid] = g_nperm[base + tid];
    if (tid < TILE) sBias[tid] = b_node[nt_ * D + tid];

    asm volatile("cp.async.wait_group 0;" ::: "memory");
    __syncthreads();

    const int wid = tid >> 5, lane = tid & 31;
    const int wm = wid & 3, wn = wid >> 2;
    const int c_base = wn * 32;
    const int lq = lane >> 2, lr = lane & 3;
    const __half* sAw = sA + wm * 64 * SROWH;

    float acc[4][4][4];
#pragma unroll
    for (int mt = 0; mt < 4; mt++)
#pragma unroll
        for (int nt = 0; nt < 4; nt++)
#pragma unroll
            for (int j = 0; j < 4; j++) acc[mt][nt][j] = 0.0f;

#pragma unroll
    for (int k0 = 0; k0 < 8; k0++) {
        const int koff = k0 * 16 + lr * 4;
        uint32_t a[4][4], bb[4][2];
#pragma unroll
        for (int mt = 0; mt < 4; mt++) {
            int row = mt * 16 + lq;
            uint2 p0 = *(const uint2*)(sAw + row * SROWH + koff);
            uint2 p1 = *(const uint2*)(sAw + (row + 8) * SROWH + koff);
            a[mt][0] = p0.x;
            a[mt][1] = p1.x;
            a[mt][2] = p0.y;
            a[mt][3] = p1.y;
        }
#pragma unroll
        for (int nt = 0; nt < 4; nt++) {
            int n = c_base + nt * 8 + lq;
            uint2 pb = *(const uint2*)(sB + n * SROWH + koff);
            bb[nt][0] = pb.x;
            bb[nt][1] = pb.y;
        }
#pragma unroll
        for (int mt = 0; mt < 4; mt++)
#pragma unroll
            for (int nt = 0; nt < 4; nt++) mma16(acc[mt][nt], a[mt], bb[nt]);
    }

    /* epilogue: float4 loads of bias+agg, float4 relu stores (pi-permuted B) */
#pragma unroll
    for (int mt = 0; mt < 4; mt++)
#pragma unroll
        for (int h = 0; h < 2; h++) {
            int rr = wm * 64 + mt * 16 + lq + h * 8;
            int n = sNode[rr];
            if (n < 0) continue;
            const float* ab = g_agg + (size_t)n * D;
            float* ob = out + (size_t)n * D;
#pragma unroll
            for (int j = 0; j < 2; j++) {
                int Lc = c_base + j * 16 + 4 * lr;
                float4 bv = *(const float4*)(sBias + Lc);
                float4 ag = *(const float4*)(ab + Lc);
                float4 o;
                o.x = fmaxf(acc[mt][2 * j][h * 2 + 0] + bv.x + ag.x, 0.0f);
                o.y = fmaxf(acc[mt][2 * j][h * 2 + 1] + bv.y + ag.y, 0.0f);
                o.z = fmaxf(acc[mt][2 * j + 1][h * 2 + 0] + bv.z + ag.z, 0.0f);
                o.w = fmaxf(acc[mt][2 * j + 1][h * 2 + 1] + bv.w + ag.w, 0.0f);
                *(float4*)(ob + Lc) = o;
            }
        }
}

/* ------------------------------ launch ------------------------------ */
extern "C" void kernel_launch(void* const* d_in, const int* in_sizes, int n_in,
                              void* d_out, int out_size) {
    const float* feats  = (const float*)d_in[0];
    const float* W_edge = (const float*)d_in[1];
    const float* b_edge = (const float*)d_in[2];
    const float* W_node = (const float*)d_in[3];
    const float* b_node = (const float*)d_in[4];
    const int* src    = (const int*)d_in[5];
    const int* dst    = (const int*)d_in[6];
    const int* ntypes = (const int*)d_in[7];
    const int* etypes = (const int*)d_in[8];
    float* out = (float*)d_out;
    (void)in_sizes; (void)n_in; (void)out_size;

    cudaFuncSetAttribute(k_edge_v15, cudaFuncAttributeMaxDynamicSharedMemorySize, EDGE_SMEM);
    cudaFuncSetAttribute(k_node_v15, cudaFuncAttributeMaxDynamicSharedMemorySize, NODE_SMEM);

    k_zero<<<2048, 256>>>(feats, W_edge, W_node);
    k_hist<<<640, 256>>>(dst, etypes, ntypes);
    k_scatter<<<320, 256>>>(src, dst, etypes, ntypes);
    k_edge_v15<<<EDGE_GRID, 512, EDGE_SMEM>>>(b_edge);
    k_node_v15<<<NODE_GRID, 512, NODE_SMEM>>>(b_node, out);
}